// round 1
// baseline (speedup 1.0000x reference)
#include <cuda_runtime.h>

// ---------------------------------------------------------------------------
// Fixed problem shape
// ---------------------------------------------------------------------------
#define BDIM 8
#define TDIM 2048
#define CDIM 512
#define HDIM 4
#define BH   32            // B*H
#define TOK  16384         // B*T
#define QKVN 6144          // 3*H*C
#define HC   2048          // H*C
#define SCALE_F 0.08838834764831845f   // (512/4)^-0.5 = 1/sqrt(128)

// ---------------------------------------------------------------------------
// Scratch (static device allocations; no cudaMalloc allowed)
// ---------------------------------------------------------------------------
__device__ float g_q[(size_t)BH * TDIM * CDIM];            // 134 MB
__device__ float g_k[(size_t)BH * TDIM * CDIM];            // 134 MB
__device__ float g_v[(size_t)BH * TDIM * CDIM];            // 134 MB
__device__ float g_s[(size_t)BH * TDIM * TDIM];            // 537 MB
__device__ float g_a[(size_t)TOK * HC];                    // 134 MB

// ---------------------------------------------------------------------------
// One tiled SGEMM core, 4 modes:
//  MODE 0: QKV   : x[16384,512] @ qkv_w[6144,512]^T  -> scatter to g_q/g_k/g_v
//  MODE 1: S     : q[T,512] @ k[T,512]^T * SCALE     -> g_s        (batch=32)
//  MODE 2: O     : s[T,T]  @ v[T,512]  (NN)          -> g_a scatter (batch=32)
//  MODE 3: PROJ  : g_a[16384,2048] @ proj_w[512,2048]^T + bias -> out
// Tile: BM=BN=128, BK=8, 256 threads, 8x8 microtile per thread.
// All dims divide the tile sizes -> no bounds checks.
// ---------------------------------------------------------------------------
template <int MODE>
__global__ __launch_bounds__(256)
void gemm_k(const float* __restrict__ X, const float* __restrict__ W,
            float* __restrict__ OUT, const float* __restrict__ bias)
{
    constexpr int M = (MODE == 0) ? TOK  : (MODE == 1) ? TDIM : (MODE == 2) ? TDIM : TOK;
    constexpr int N = (MODE == 0) ? QKVN : (MODE == 1) ? TDIM : (MODE == 2) ? CDIM : CDIM;
    constexpr int K = (MODE == 0) ? CDIM : (MODE == 1) ? CDIM : (MODE == 2) ? TDIM : HC;
    constexpr bool BT = (MODE != 2);   // B operand is [N,K] (NT) except O-gemm (NN: [K,N])
    (void)M;

    __shared__ float As[8][128];
    __shared__ float Bs[8][128];

    const int tid = threadIdx.x;
    const int m0  = blockIdx.y * 128;
    const int n0  = blockIdx.x * 128;
    const size_t z = blockIdx.z;

    // Resolve batched operand base pointers
    const float* Ab;
    const float* Bb;
    if (MODE == 0)      { Ab = X;                            Bb = W; }
    else if (MODE == 1) { Ab = g_q + z * (size_t)TDIM * CDIM; Bb = g_k + z * (size_t)TDIM * CDIM; }
    else if (MODE == 2) { Ab = g_s + z * (size_t)TDIM * TDIM; Bb = g_v + z * (size_t)TDIM * CDIM; }
    else                { Ab = g_a;                          Bb = W; }

    // load indices: NT-style operand (row-major [rows,K]) loads a float4 along K
    const int lr = tid >> 1;           // 0..127 (row within tile)
    const int lc = (tid & 1) * 4;      // 0 or 4 (k offset)
    // NN-style B operand (row-major [K,N]) loads a float4 along N
    const int br = tid >> 5;           // 0..7   (k row)
    const int bc = (tid & 31) * 4;     // 0..124 (n col)

    const int tx = (tid & 15) * 8;     // micro-tile col base
    const int ty = (tid >> 4) * 8;     // micro-tile row base

    float acc[8][8];
#pragma unroll
    for (int i = 0; i < 8; i++)
#pragma unroll
        for (int j = 0; j < 8; j++) acc[i][j] = 0.f;

    for (int k0 = 0; k0 < K; k0 += 8) {
        // --- A tile (always row-major [M,K], lda = K) -> As[k][m]
        float4 av = *(const float4*)(Ab + (size_t)(m0 + lr) * K + k0 + lc);
        As[lc + 0][lr] = av.x;
        As[lc + 1][lr] = av.y;
        As[lc + 2][lr] = av.z;
        As[lc + 3][lr] = av.w;

        // --- B tile -> Bs[k][n]
        if (BT) {
            float4 bv = *(const float4*)(Bb + (size_t)(n0 + lr) * K + k0 + lc);
            Bs[lc + 0][lr] = bv.x;
            Bs[lc + 1][lr] = bv.y;
            Bs[lc + 2][lr] = bv.z;
            Bs[lc + 3][lr] = bv.w;
        } else {
            float4 bv = *(const float4*)(Bb + (size_t)(k0 + br) * N + n0 + bc);
            *(float4*)&Bs[br][bc] = bv;
        }
        __syncthreads();

#pragma unroll
        for (int kk = 0; kk < 8; kk++) {
            float a[8], b[8];
            *(float4*)(a)     = *(const float4*)&As[kk][ty];
            *(float4*)(a + 4) = *(const float4*)&As[kk][ty + 4];
            *(float4*)(b)     = *(const float4*)&Bs[kk][tx];
            *(float4*)(b + 4) = *(const float4*)&Bs[kk][tx + 4];
#pragma unroll
            for (int i = 0; i < 8; i++)
#pragma unroll
                for (int j = 0; j < 8; j++)
                    acc[i][j] = fmaf(a[i], b[j], acc[i][j]);
        }
        __syncthreads();
    }

    // ------------------------------------------------------------------ epilogue
    if (MODE == 0) {
        // column j of [16384,6144]: s = j>>11, h = (j>>9)&3, c = j&511
        // a 128-wide tile never crosses an (s,h) boundary (512 | tile grid)
        const int s     = n0 >> 11;
        const int h     = (n0 >> 9) & 3;
        const int cbase = (n0 & 511) + tx;
        const int b     = m0 >> 11;                // row m = b*2048 + t
        const int tbase = (m0 & 2047) + ty;
        float* dst = (s == 0) ? g_q : (s == 1) ? g_k : g_v;
        const size_t headbase = (size_t)(b * 4 + h) * TDIM * CDIM;
#pragma unroll
        for (int i = 0; i < 8; i++) {
            size_t roff = headbase + (size_t)(tbase + i) * CDIM + cbase;
#pragma unroll
            for (int j = 0; j < 8; j++) dst[roff + j] = acc[i][j];
        }
    } else if (MODE == 1) {
        float* cb = g_s + z * (size_t)TDIM * TDIM;
#pragma unroll
        for (int i = 0; i < 8; i++) {
            size_t roff = (size_t)(m0 + ty + i) * TDIM + n0 + tx;
#pragma unroll
            for (int j = 0; j < 8; j++) cb[roff + j] = acc[i][j] * SCALE_F;
        }
    } else if (MODE == 2) {
        // write attn output already transposed for proj: row (b*T+t), col h*512+c
        const int b = (int)z >> 2;
        const int h = (int)z & 3;
#pragma unroll
        for (int i = 0; i < 8; i++) {
            size_t roff = (size_t)(b * TDIM + m0 + ty + i) * HC + h * CDIM + n0 + tx;
#pragma unroll
            for (int j = 0; j < 8; j++) g_a[roff + j] = acc[i][j];
        }
    } else {
#pragma unroll
        for (int i = 0; i < 8; i++) {
            size_t roff = (size_t)(m0 + ty + i) * CDIM + n0 + tx;
#pragma unroll
            for (int j = 0; j < 8; j++) OUT[roff + j] = acc[i][j] + bias[n0 + tx + j];
        }
    }
}

// ---------------------------------------------------------------------------
// Row softmax over g_s (in place). One block per row of 2048.
// ---------------------------------------------------------------------------
__global__ __launch_bounds__(256)
void softmax_k()
{
    const size_t row = blockIdx.x;               // 0 .. BH*T-1
    float* p = g_s + row * TDIM;
    const int tid = threadIdx.x;

    __shared__ float red[256];

    float v[8];
    float m = -1e30f;
#pragma unroll
    for (int i = 0; i < 8; i++) {
        v[i] = p[tid + i * 256];
        m = fmaxf(m, v[i]);
    }
    red[tid] = m;
    __syncthreads();
#pragma unroll
    for (int s = 128; s > 0; s >>= 1) {
        if (tid < s) red[tid] = fmaxf(red[tid], red[tid + s]);
        __syncthreads();
    }
    m = red[0];
    __syncthreads();

    float sum = 0.f;
#pragma unroll
    for (int i = 0; i < 8; i++) {
        v[i] = expf(v[i] - m);
        sum += v[i];
    }
    red[tid] = sum;
    __syncthreads();
#pragma unroll
    for (int s = 128; s > 0; s >>= 1) {
        if (tid < s) red[tid] += red[tid + s];
        __syncthreads();
    }
    const float inv = 1.f / red[0];
#pragma unroll
    for (int i = 0; i < 8; i++) p[tid + i * 256] = v[i] * inv;
}

// ---------------------------------------------------------------------------
// kernel_launch: 5 graph-capturable launches, no allocations.
// Inputs (metadata order): x, qkv_w, proj_w, proj_b. Output: [B,T,C] fp32.
// ---------------------------------------------------------------------------
extern "C" void kernel_launch(void* const* d_in, const int* in_sizes, int n_in,
                              void* d_out, int out_size)
{
    const float* x      = (const float*)d_in[0];
    const float* qkv_w  = (const float*)d_in[1];
    const float* proj_w = (const float*)d_in[2];
    const float* proj_b = (const float*)d_in[3];
    float* out = (float*)d_out;
    (void)in_sizes; (void)n_in; (void)out_size;

    dim3 blk(256);

    // 1) QKV projection + scatter into per-head q/k/v
    gemm_k<0><<<dim3(QKVN / 128, TOK / 128, 1), blk>>>(x, qkv_w, nullptr, nullptr);

    // 2) S = Q K^T * SCALE  (batched over 32 heads)
    gemm_k<1><<<dim3(TDIM / 128, TDIM / 128, BH), blk>>>(nullptr, nullptr, nullptr, nullptr);

    // 3) row softmax in place
    softmax_k<<<BH * TDIM, 256>>>();

    // 4) O = P V, scattered into proj-ready layout [B*T, H*C]
    gemm_k<2><<<dim3(CDIM / 128, TDIM / 128, BH), blk>>>(nullptr, nullptr, nullptr, nullptr);

    // 5) final projection + bias
    gemm_k<3><<<dim3(CDIM / 128, TOK / 128, 1), blk>>>(nullptr, proj_w, out, proj_b);
}

// round 5
// speedup vs baseline: 2.2430x; 2.2430x over previous
#include <cuda_runtime.h>
#include <cuda_bf16.h>
#include <cstdint>

// ---------------------------------------------------------------------------
// Fixed problem shape
// ---------------------------------------------------------------------------
#define TDIM 2048
#define CDIM 512
#define BH   32            // B*H
#define TOK  16384         // B*T
#define QKVN 6144          // 3*H*C
#define HC   2048          // H*C
#define SCALE_F 0.08838834764831845f   // 1/sqrt(128)

// ---------------------------------------------------------------------------
// Scratch (static device arrays; no cudaMalloc allowed)
// ---------------------------------------------------------------------------
__device__ float g_q [(size_t)BH * TDIM * CDIM];   // [bh][t][c]
__device__ float g_k [(size_t)BH * TDIM * CDIM];   // [bh][t][c]
__device__ float g_vt[(size_t)BH * CDIM * TDIM];   // [bh][c][t]  (V transposed)
__device__ float g_s [(size_t)BH * TDIM * TDIM];   // [bh][q][k]
__device__ float g_a [(size_t)TOK * HC];           // [b*t][h*c]

// ---------------------------------------------------------------------------
// Smem layout: 2 stages x (A_hi | A_lo | B_hi | B_lo), rows padded to 40 bf16
// (80-byte rows: multiple of 16 so every ldmatrix lane address is aligned;
//  stride of 20 words keeps all 8 rows of each ldmatrix phase on distinct banks)
// ---------------------------------------------------------------------------
#define ROWPAD 40                       // 32 bf16 + 8 pad (80B rows)
#define TILE_ELEMS (128 * ROWPAD)       // 5120 bf16 = 10240 B
#define STAGE_ELEMS (4 * TILE_ELEMS)    // 20480 bf16 = 40960 B
#define SMEM_BYTES (2 * STAGE_ELEMS * 2)  // 81920 B

#define OFF_AHI 0
#define OFF_ALO (TILE_ELEMS)
#define OFF_BHI (2 * TILE_ELEMS)
#define OFF_BLO (3 * TILE_ELEMS)

// ---------------------------------------------------------------------------
// PTX helpers (all base sm_80-class instructions; no 'a'-suffix features)
// ---------------------------------------------------------------------------
__device__ __forceinline__ uint32_t smem_u32(const void* p) {
    uint32_t a;
    asm("{ .reg .u64 t; cvta.to.shared.u64 t, %1; cvt.u32.u64 %0, t; }" : "=r"(a) : "l"(p));
    return a;
}
__device__ __forceinline__ void ldsm4(uint32_t* r, uint32_t addr) {
    asm volatile("ldmatrix.sync.aligned.m8n8.x4.shared.b16 {%0,%1,%2,%3}, [%4];"
                 : "=r"(r[0]), "=r"(r[1]), "=r"(r[2]), "=r"(r[3]) : "r"(addr));
}
__device__ __forceinline__ void ldsm2(uint32_t* r, uint32_t addr) {
    asm volatile("ldmatrix.sync.aligned.m8n8.x2.shared.b16 {%0,%1}, [%2];"
                 : "=r"(r[0]), "=r"(r[1]) : "r"(addr));
}
__device__ __forceinline__ void mma_bf16(float* c, const uint32_t* a, const uint32_t* b) {
    asm volatile("mma.sync.aligned.m16n8k16.row.col.f32.bf16.bf16.f32 "
                 "{%0,%1,%2,%3}, {%4,%5,%6,%7}, {%8,%9}, {%0,%1,%2,%3};"
                 : "+f"(c[0]), "+f"(c[1]), "+f"(c[2]), "+f"(c[3])
                 : "r"(a[0]), "r"(a[1]), "r"(a[2]), "r"(a[3]), "r"(b[0]), "r"(b[1]));
}

// split one fp32 into (hi, lo) bf16 pair
__device__ __forceinline__ void split2(float x, __nv_bfloat16& h, __nv_bfloat16& l) {
    h = __float2bfloat16_rn(x);
    l = __float2bfloat16_rn(x - __bfloat162float(h));
}
// convert float4 -> two packed uint32 (hi) and (lo) quads, store 8B each
__device__ __forceinline__ void split_store(const float4& v,
                                            __nv_bfloat16* hi, __nv_bfloat16* lo, int idx) {
    __nv_bfloat162 h0, h1, l0, l1;
    split2(v.x, h0.x, l0.x);
    split2(v.y, h0.y, l0.y);
    split2(v.z, h1.x, l1.x);
    split2(v.w, h1.y, l1.y);
    uint2 hp = make_uint2(*(uint32_t*)&h0, *(uint32_t*)&h1);
    uint2 lp = make_uint2(*(uint32_t*)&l0, *(uint32_t*)&l1);
    *(uint2*)(hi + idx) = hp;
    *(uint2*)(lo + idx) = lp;
}

// ---------------------------------------------------------------------------
// mma.sync bf16-split GEMM core, 4 modes:
//  MODE 0: QKV : x[16384,512] @ qkv_w[6144,512]^T -> g_q / g_k / g_vt(scatter^T)
//  MODE 1: S   : q[T,512] @ k[T,512]^T * SCALE    -> g_s        (z = head)
//  MODE 2: O   : p[T,T]  @ vt[512,2048]^T         -> g_a scatter (z = head)
//  MODE 3: PROJ: g_a[16384,2048] @ proj_w[512,2048]^T + bias -> out
// All modes: A row-major [M,K], B row-major [N,K]. Tile 128x128, BK=32.
// ---------------------------------------------------------------------------
template <int MODE>
__global__ __launch_bounds__(256)
void mgemm(const float* __restrict__ X, const float* __restrict__ W,
           float* __restrict__ OUT, const float* __restrict__ bias)
{
    constexpr int K = (MODE == 0) ? CDIM : (MODE == 1) ? CDIM : (MODE == 2) ? TDIM : HC;
    constexpr int NITER = K / 32;

    extern __shared__ __nv_bfloat16 sm[];
    const uint32_t sb = smem_u32(sm);

    const int tid  = threadIdx.x;
    const int wid  = tid >> 5;
    const int lane = tid & 31;
    const int wm   = wid & 1;       // 0/1 -> m offset 0/64
    const int wn   = wid >> 1;      // 0..3 -> n offset *32
    const int m0   = blockIdx.y * 128;
    const int n0   = blockIdx.x * 128;
    const size_t z = blockIdx.z;

    const float* Ab;
    const float* Bb;
    if (MODE == 0)      { Ab = X;                              Bb = W; }
    else if (MODE == 1) { Ab = g_q + z * (size_t)TDIM * CDIM;  Bb = g_k  + z * (size_t)TDIM * CDIM; }
    else if (MODE == 2) { Ab = g_s + z * (size_t)TDIM * TDIM;  Bb = g_vt + z * (size_t)CDIM * TDIM; }
    else                { Ab = g_a;                            Bb = W; }

    // global load coordinates: 128 rows x 32 floats, 2 threads/row, 4 float4 each
    const int lrow = tid >> 1;
    const int lcol = (tid & 1) * 16;
    const float* agp = Ab + (size_t)(m0 + lrow) * K + lcol;
    const float* bgp = Bb + (size_t)(n0 + lrow) * K + lcol;

    float acc[4][4][4];
#pragma unroll
    for (int i = 0; i < 4; i++)
#pragma unroll
        for (int j = 0; j < 4; j++)
#pragma unroll
            for (int c = 0; c < 4; c++) acc[i][j][c] = 0.f;

    float4 pa[4], pb[4];

    // ---- preload tile 0
#pragma unroll
    for (int q = 0; q < 4; q++) {
        pa[q] = *(const float4*)(agp + q * 4);
        pb[q] = *(const float4*)(bgp + q * 4);
    }
    {
        __nv_bfloat16* st = sm;           // stage 0
        const int idx = lrow * ROWPAD + lcol;
#pragma unroll
        for (int q = 0; q < 4; q++) {
            split_store(pa[q], st + OFF_AHI, st + OFF_ALO, idx + q * 4);
            split_store(pb[q], st + OFF_BHI, st + OFF_BLO, idx + q * 4);
        }
    }
    __syncthreads();

    for (int it = 0; it < NITER; ++it) {
        // prefetch next tile into registers (overlaps with MMA below)
        if (it + 1 < NITER) {
            const int k0 = (it + 1) * 32;
#pragma unroll
            for (int q = 0; q < 4; q++) {
                pa[q] = *(const float4*)(agp + k0 + q * 4);
                pb[q] = *(const float4*)(bgp + k0 + q * 4);
            }
        }

        // ---- MMAs over current stage
        const uint32_t stage = sb + (uint32_t)((it & 1) * STAGE_ELEMS * 2);
#pragma unroll
        for (int ks = 0; ks < 2; ks++) {
            uint32_t ah[4][4], al[4][4];
            const int arow = wm * 64 + (lane & 15);
            const int akoff = ks * 16 + (lane >> 4) * 8;
#pragma unroll
            for (int mt = 0; mt < 4; mt++) {
                const uint32_t ao = stage + (uint32_t)(((arow + mt * 16) * ROWPAD + akoff) * 2);
                ldsm4(ah[mt], ao + OFF_AHI * 2);
                ldsm4(al[mt], ao + OFF_ALO * 2);
            }
            const int brow = wn * 32 + (lane & 7);
            const int bkoff = ks * 16 + ((lane >> 3) & 1) * 8;
#pragma unroll
            for (int nt = 0; nt < 4; nt++) {
                uint32_t bh[2], bl[2];
                const uint32_t bo = stage + (uint32_t)(((brow + nt * 8) * ROWPAD + bkoff) * 2);
                ldsm2(bh, bo + OFF_BHI * 2);
                ldsm2(bl, bo + OFF_BLO * 2);
#pragma unroll
                for (int mt = 0; mt < 4; mt++) {
                    mma_bf16(acc[mt][nt], ah[mt], bh);
                    mma_bf16(acc[mt][nt], al[mt], bh);
                    mma_bf16(acc[mt][nt], ah[mt], bl);
                }
            }
        }

        // ---- convert + store next tile into other stage
        if (it + 1 < NITER) {
            __nv_bfloat16* st = sm + ((it + 1) & 1) * STAGE_ELEMS;
            const int idx = lrow * ROWPAD + lcol;
#pragma unroll
            for (int q = 0; q < 4; q++) {
                split_store(pa[q], st + OFF_AHI, st + OFF_ALO, idx + q * 4);
                split_store(pb[q], st + OFF_BHI, st + OFF_BLO, idx + q * 4);
            }
        }
        __syncthreads();
    }

    // ------------------------------------------------------------- epilogue
    const int g   = lane >> 2;
    const int tig = lane & 3;

#pragma unroll
    for (int mt = 0; mt < 4; mt++) {
#pragma unroll
        for (int nt = 0; nt < 4; nt++) {
            const int r0 = m0 + wm * 64 + mt * 16 + g;       // global row (m)
            const int c0 = n0 + wn * 32 + nt * 8 + tig * 2;  // global col (n)
            float* ac = acc[mt][nt];

            if (MODE == 0) {
                const int s = n0 >> 11;            // 0:q 1:k 2:v
                const int h = (n0 >> 9) & 3;
                const int cc = (c0 & 511);
                const int b = m0 >> 11;
                const int t = r0 & 2047;
                const size_t head = (size_t)(b * 4 + h);
                if (s < 2) {
                    float* dst = (s == 0) ? g_q : g_k;
                    float* p0 = dst + (head * TDIM + t) * CDIM + cc;
                    *(float2*)p0 = make_float2(ac[0], ac[1]);
                    *(float2*)(p0 + 8 * CDIM) = make_float2(ac[2], ac[3]);
                } else {
                    // transposed: g_vt[head][c][t]
                    float* vb = g_vt + head * (size_t)CDIM * TDIM;
                    vb[(size_t)(cc + 0) * TDIM + t]     = ac[0];
                    vb[(size_t)(cc + 1) * TDIM + t]     = ac[1];
                    vb[(size_t)(cc + 0) * TDIM + t + 8] = ac[2];
                    vb[(size_t)(cc + 1) * TDIM + t + 8] = ac[3];
                }
            } else if (MODE == 1) {
                float* p0 = g_s + z * (size_t)TDIM * TDIM + (size_t)r0 * TDIM + c0;
                *(float2*)p0 = make_float2(ac[0] * SCALE_F, ac[1] * SCALE_F);
                *(float2*)(p0 + 8 * TDIM) = make_float2(ac[2] * SCALE_F, ac[3] * SCALE_F);
            } else if (MODE == 2) {
                const int b = (int)z >> 2;
                const int h = (int)z & 3;
                float* p0 = g_a + ((size_t)(b * TDIM + r0)) * HC + h * CDIM + c0;
                *(float2*)p0 = make_float2(ac[0], ac[1]);
                *(float2*)(p0 + 8 * HC) = make_float2(ac[2], ac[3]);
            } else {
                const float2 bi = *(const float2*)(bias + c0);
                float* p0 = OUT + (size_t)r0 * CDIM + c0;
                *(float2*)p0 = make_float2(ac[0] + bi.x, ac[1] + bi.y);
                *(float2*)(p0 + 8 * CDIM) = make_float2(ac[2] + bi.x, ac[3] + bi.y);
            }
        }
    }
}

// ---------------------------------------------------------------------------
// Row softmax over g_s (in place). One block per row of 2048.
// ---------------------------------------------------------------------------
__global__ __launch_bounds__(256)
void softmax_k()
{
    const size_t row = blockIdx.x;
    float* p = g_s + row * TDIM;
    const int tid = threadIdx.x;

    __shared__ float red[256];

    float v[8];
    float m = -1e30f;
#pragma unroll
    for (int i = 0; i < 8; i++) {
        v[i] = p[tid + i * 256];
        m = fmaxf(m, v[i]);
    }
    red[tid] = m;
    __syncthreads();
#pragma unroll
    for (int s = 128; s > 0; s >>= 1) {
        if (tid < s) red[tid] = fmaxf(red[tid], red[tid + s]);
        __syncthreads();
    }
    m = red[0];
    __syncthreads();

    float sum = 0.f;
#pragma unroll
    for (int i = 0; i < 8; i++) {
        v[i] = expf(v[i] - m);
        sum += v[i];
    }
    red[tid] = sum;
    __syncthreads();
#pragma unroll
    for (int s = 128; s > 0; s >>= 1) {
        if (tid < s) red[tid] += red[tid + s];
        __syncthreads();
    }
    const float inv = 1.f / red[0];
#pragma unroll
    for (int i = 0; i < 8; i++) p[tid + i * 256] = v[i] * inv;
}

// ---------------------------------------------------------------------------
// kernel_launch: 5 graph-capturable launches, no allocations.
// ---------------------------------------------------------------------------
extern "C" void kernel_launch(void* const* d_in, const int* in_sizes, int n_in,
                              void* d_out, int out_size)
{
    const float* x      = (const float*)d_in[0];
    const float* qkv_w  = (const float*)d_in[1];
    const float* proj_w = (const float*)d_in[2];
    const float* proj_b = (const float*)d_in[3];
    float* out = (float*)d_out;
    (void)in_sizes; (void)n_in; (void)out_size;

    // unconditional every call (deterministic; not a stream op, capture-safe)
    cudaFuncSetAttribute(mgemm<0>, cudaFuncAttributeMaxDynamicSharedMemorySize, SMEM_BYTES);
    cudaFuncSetAttribute(mgemm<1>, cudaFuncAttributeMaxDynamicSharedMemorySize, SMEM_BYTES);
    cudaFuncSetAttribute(mgemm<2>, cudaFuncAttributeMaxDynamicSharedMemorySize, SMEM_BYTES);
    cudaFuncSetAttribute(mgemm<3>, cudaFuncAttributeMaxDynamicSharedMemorySize, SMEM_BYTES);

    dim3 blk(256);

    // 1) QKV projection; writes g_q, g_k, g_vt (V transposed)
    mgemm<0><<<dim3(QKVN / 128, TOK / 128, 1), blk, SMEM_BYTES>>>(x, qkv_w, nullptr, nullptr);
    // 2) S = Q K^T * SCALE
    mgemm<1><<<dim3(TDIM / 128, TDIM / 128, BH), blk, SMEM_BYTES>>>(nullptr, nullptr, nullptr, nullptr);
    // 3) softmax rows (in place)
    softmax_k<<<BH * TDIM, 256>>>();
    // 4) O = P V  (B = V^T rows), scatter into proj-ready [B*T, H*C]
    mgemm<2><<<dim3(CDIM / 128, TDIM / 128, BH), blk, SMEM_BYTES>>>(nullptr, nullptr, nullptr, nullptr);
    // 5) final projection + bias
    mgemm<3><<<dim3(CDIM / 128, TOK / 128, 1), blk, SMEM_BYTES>>>(nullptr, proj_w, out, proj_b);
}

// round 6
// speedup vs baseline: 2.2761x; 1.0148x over previous
#include <cuda_runtime.h>
#include <cuda_bf16.h>
#include <cstdint>

// ---------------------------------------------------------------------------
// Fixed problem shape
// ---------------------------------------------------------------------------
#define TDIM 2048
#define CDIM 512
#define BH   32            // B*H
#define TOK  16384         // B*T
#define QKVN 6144          // 3*H*C
#define HC   2048          // H*C
#define SCALE_F 0.08838834764831845f   // 1/sqrt(128)

typedef __nv_bfloat16 bf16;
typedef __nv_bfloat162 bf162;

// ---------------------------------------------------------------------------
// Scratch (static device arrays; no cudaMalloc allowed)
// All GEMM operands live as pre-split bf16 (hi, lo) pairs.
// ---------------------------------------------------------------------------
__device__ bf16 xs_hi [(size_t)TOK * CDIM];
__device__ bf16 xs_lo [(size_t)TOK * CDIM];
__device__ bf16 ws_hi [(size_t)QKVN * CDIM];
__device__ bf16 ws_lo [(size_t)QKVN * CDIM];
__device__ bf16 pws_hi[(size_t)CDIM * HC];
__device__ bf16 pws_lo[(size_t)CDIM * HC];

__device__ bf16 q_hi [(size_t)BH * TDIM * CDIM];   // [bh][t][c], SCALE folded in
__device__ bf16 q_lo [(size_t)BH * TDIM * CDIM];
__device__ bf16 k_hi [(size_t)BH * TDIM * CDIM];
__device__ bf16 k_lo [(size_t)BH * TDIM * CDIM];
__device__ bf16 vt_hi[(size_t)BH * CDIM * TDIM];   // [bh][c][t]
__device__ bf16 vt_lo[(size_t)BH * CDIM * TDIM];

__device__ float g_s [(size_t)BH * TDIM * TDIM];   // scores (scaled), fp32
__device__ bf16 p_hi [(size_t)BH * TDIM * TDIM];   // softmax(S)
__device__ bf16 p_lo [(size_t)BH * TDIM * TDIM];

__device__ bf16 a_hi [(size_t)TOK * HC];           // attn out, proj layout
__device__ bf16 a_lo [(size_t)TOK * HC];

// ---------------------------------------------------------------------------
// Smem: NS stages x (A_hi | A_lo | B_hi | B_lo) tiles, rows padded to 40 bf16
// 80-byte rows: 16B-aligned for ldmatrix/cp.async, conflict-free ldsm phases.
// ---------------------------------------------------------------------------
#define ROWPAD 40
#define TILE_BYTES (128 * ROWPAD * 2)     // 10240
#define STAGE_BYTES (4 * TILE_BYTES)      // 40960
#define NS 3
#define SMEM_BYTES (NS * STAGE_BYTES)     // 122880

#define OFF_AHI 0
#define OFF_ALO TILE_BYTES
#define OFF_BHI (2 * TILE_BYTES)
#define OFF_BLO (3 * TILE_BYTES)

// ---------------------------------------------------------------------------
// PTX helpers (base sm_80-class; no 'a'-suffix features)
// ---------------------------------------------------------------------------
__device__ __forceinline__ uint32_t smem_u32(const void* p) {
    uint32_t a;
    asm("{ .reg .u64 t; cvta.to.shared.u64 t, %1; cvt.u32.u64 %0, t; }" : "=r"(a) : "l"(p));
    return a;
}
__device__ __forceinline__ void cpa16(uint32_t dst, const void* src) {
    asm volatile("cp.async.ca.shared.global [%0], [%1], 16;" :: "r"(dst), "l"(src));
}
__device__ __forceinline__ void cp_commit() {
    asm volatile("cp.async.commit_group;" ::: "memory");
}
template <int N>
__device__ __forceinline__ void cp_wait() {
    asm volatile("cp.async.wait_group %0;" :: "n"(N) : "memory");
}
__device__ __forceinline__ void ldsm4(uint32_t* r, uint32_t addr) {
    asm volatile("ldmatrix.sync.aligned.m8n8.x4.shared.b16 {%0,%1,%2,%3}, [%4];"
                 : "=r"(r[0]), "=r"(r[1]), "=r"(r[2]), "=r"(r[3]) : "r"(addr));
}
__device__ __forceinline__ void ldsm2(uint32_t* r, uint32_t addr) {
    asm volatile("ldmatrix.sync.aligned.m8n8.x2.shared.b16 {%0,%1}, [%2];"
                 : "=r"(r[0]), "=r"(r[1]) : "r"(addr));
}
__device__ __forceinline__ void mma_bf16(float* c, const uint32_t* a, const uint32_t* b) {
    asm volatile("mma.sync.aligned.m16n8k16.row.col.f32.bf16.bf16.f32 "
                 "{%0,%1,%2,%3}, {%4,%5,%6,%7}, {%8,%9}, {%0,%1,%2,%3};"
                 : "+f"(c[0]), "+f"(c[1]), "+f"(c[2]), "+f"(c[3])
                 : "r"(a[0]), "r"(a[1]), "r"(a[2]), "r"(a[3]), "r"(b[0]), "r"(b[1]));
}
__device__ __forceinline__ void split2(float x, bf16& h, bf16& l) {
    h = __float2bfloat16_rn(x);
    l = __float2bfloat16_rn(x - __bfloat162float(h));
}

// ---------------------------------------------------------------------------
// Elementwise fp32 -> (hi, lo) bf16 splitter for kernel inputs
// ---------------------------------------------------------------------------
__global__ __launch_bounds__(256)
void split_k(const float* __restrict__ src, bf16* __restrict__ hi,
             bf16* __restrict__ lo, size_t n)
{
    size_t i = ((size_t)blockIdx.x * 256 + threadIdx.x) * 4;
    if (i >= n) return;
    float4 v = *(const float4*)(src + i);
    bf162 h0, h1, l0, l1;
    split2(v.x, h0.x, l0.x);
    split2(v.y, h0.y, l0.y);
    split2(v.z, h1.x, l1.x);
    split2(v.w, h1.y, l1.y);
    *(bf162*)(hi + i)     = h0;
    *(bf162*)(hi + i + 2) = h1;
    *(bf162*)(lo + i)     = l0;
    *(bf162*)(lo + i + 2) = l1;
}

// ---------------------------------------------------------------------------
// mma.sync bf16-split GEMM, cp.async 3-stage pipeline. Modes:
//  MODE 0: QKV : xs[16384,512] @ ws[6144,512]^T -> q(,*SCALE)/k/vt hi+lo
//  MODE 1: S   : q[T,512] @ k[T,512]^T          -> g_s fp32  (z = head)
//  MODE 2: O   : p[T,T]  @ vt[512,2048]^T       -> a hi+lo   (z = head)
//  MODE 3: PROJ: a[16384,2048] @ pws[512,2048]^T + bias -> out fp32
// A, B row-major [rows, K] bf16 hi/lo. Tile 128x128, BK=32, 256 threads.
// ---------------------------------------------------------------------------
template <int MODE>
__global__ __launch_bounds__(256)
void mgemm(float* __restrict__ OUT, const float* __restrict__ bias)
{
    constexpr int K = (MODE <= 1) ? CDIM : TDIM;   // MODE3 uses HC=2048=TDIM
    constexpr int NITER = K / 32;

    extern __shared__ char smc[];
    const uint32_t sb = smem_u32(smc);

    const int tid  = threadIdx.x;
    const int wid  = tid >> 5;
    const int lane = tid & 31;
    const int wm   = wid & 1;
    const int wn   = wid >> 1;
    const int m0   = blockIdx.y * 128;
    const int n0   = blockIdx.x * 128;
    const size_t z = blockIdx.z;

    const bf16 *Ah, *Al, *Bh, *Bl;
    if (MODE == 0)      { Ah = xs_hi;  Al = xs_lo;  Bh = ws_hi;  Bl = ws_lo; }
    else if (MODE == 1) {
        Ah = q_hi + z * (size_t)TDIM * CDIM; Al = q_lo + z * (size_t)TDIM * CDIM;
        Bh = k_hi + z * (size_t)TDIM * CDIM; Bl = k_lo + z * (size_t)TDIM * CDIM;
    } else if (MODE == 2) {
        Ah = p_hi + z * (size_t)TDIM * TDIM; Al = p_lo + z * (size_t)TDIM * TDIM;
        Bh = vt_hi + z * (size_t)CDIM * TDIM; Bl = vt_lo + z * (size_t)CDIM * TDIM;
    } else              { Ah = a_hi;  Al = a_lo;  Bh = pws_hi; Bl = pws_lo; }

    // loader geometry: r = row 0..127, hh = 0/16 (bf16 elems); 32B per (r,hh)
    const int lr = tid >> 1;
    const int lh = (tid & 1) * 16;
    const bf16* agh = Ah + (size_t)(m0 + lr) * K + lh;
    const bf16* agl = Al + (size_t)(m0 + lr) * K + lh;
    const bf16* bgh = Bh + (size_t)(n0 + lr) * K + lh;
    const bf16* bgl = Bl + (size_t)(n0 + lr) * K + lh;
    const uint32_t dstb = sb + (uint32_t)((lr * ROWPAD + lh) * 2);

#define ISSUE_STAGE(kt, buf) do {                                             \
        const int _k0 = (kt) * 32;                                            \
        const uint32_t _d = dstb + (uint32_t)((buf) * STAGE_BYTES);           \
        cpa16(_d + OFF_AHI,      agh + _k0);                                  \
        cpa16(_d + OFF_AHI + 16, agh + _k0 + 8);                              \
        cpa16(_d + OFF_ALO,      agl + _k0);                                  \
        cpa16(_d + OFF_ALO + 16, agl + _k0 + 8);                              \
        cpa16(_d + OFF_BHI,      bgh + _k0);                                  \
        cpa16(_d + OFF_BHI + 16, bgh + _k0 + 8);                              \
        cpa16(_d + OFF_BLO,      bgl + _k0);                                  \
        cpa16(_d + OFF_BLO + 16, bgl + _k0 + 8);                              \
    } while (0)

    float acc[4][4][4];
#pragma unroll
    for (int i = 0; i < 4; i++)
#pragma unroll
        for (int j = 0; j < 4; j++)
#pragma unroll
            for (int c = 0; c < 4; c++) acc[i][j][c] = 0.f;

    // prologue: stages 0 .. NS-2
#pragma unroll
    for (int s = 0; s < NS - 1; s++) {
        ISSUE_STAGE(s, s);
        cp_commit();
    }

    for (int it = 0; it < NITER; ++it) {
        cp_wait<NS - 2>();          // stage `it` resident
        __syncthreads();            // all warps done reading stage it-1

        const int is = it + NS - 1; // refill buffer consumed at it-1
        if (is < NITER) {
            ISSUE_STAGE(is, is % NS);
            cp_commit();
        }

        const uint32_t stage = sb + (uint32_t)((it % NS) * STAGE_BYTES);
#pragma unroll
        for (int ks = 0; ks < 2; ks++) {
            uint32_t ah[4][4], al[4][4];
            const int arow = wm * 64 + (lane & 15);
            const int akoff = ks * 16 + (lane >> 4) * 8;
#pragma unroll
            for (int mt = 0; mt < 4; mt++) {
                const uint32_t ao = stage + (uint32_t)(((arow + mt * 16) * ROWPAD + akoff) * 2);
                ldsm4(ah[mt], ao + OFF_AHI);
                ldsm4(al[mt], ao + OFF_ALO);
            }
            const int brow = wn * 32 + (lane & 7);
            const int bkoff = ks * 16 + ((lane >> 3) & 1) * 8;
#pragma unroll
            for (int nt = 0; nt < 4; nt++) {
                uint32_t bh[2], bl[2];
                const uint32_t bo = stage + (uint32_t)(((brow + nt * 8) * ROWPAD + bkoff) * 2);
                ldsm2(bh, bo + OFF_BHI);
                ldsm2(bl, bo + OFF_BLO);
#pragma unroll
                for (int mt = 0; mt < 4; mt++) {
                    mma_bf16(acc[mt][nt], ah[mt], bh);
                    mma_bf16(acc[mt][nt], al[mt], bh);
                    mma_bf16(acc[mt][nt], ah[mt], bl);
                }
            }
        }
    }
#undef ISSUE_STAGE

    // ------------------------------------------------------------- epilogue
    const int g   = lane >> 2;
    const int tig = lane & 3;

#pragma unroll
    for (int mt = 0; mt < 4; mt++) {
#pragma unroll
        for (int nt = 0; nt < 4; nt++) {
            const int r0 = m0 + wm * 64 + mt * 16 + g;
            const int c0 = n0 + wn * 32 + nt * 8 + tig * 2;
            float* ac = acc[mt][nt];

            if (MODE == 0) {
                const int s = n0 >> 11;            // 0:q 1:k 2:v
                const int h = (n0 >> 9) & 3;
                const int cc = c0 & 511;
                const int b = m0 >> 11;
                const int t = r0 & 2047;
                const size_t head = (size_t)(b * 4 + h);
                const float sc = (s == 0) ? SCALE_F : 1.f;
                bf162 h0, h1, l0, l1;
                split2(ac[0] * sc, h0.x, l0.x);
                split2(ac[1] * sc, h0.y, l0.y);
                split2(ac[2] * sc, h1.x, l1.x);
                split2(ac[3] * sc, h1.y, l1.y);
                if (s < 2) {
                    bf16* dh = ((s == 0) ? q_hi : k_hi) + (head * TDIM + t) * CDIM + cc;
                    bf16* dl = ((s == 0) ? q_lo : k_lo) + (head * TDIM + t) * CDIM + cc;
                    *(bf162*)dh = h0;
                    *(bf162*)dl = l0;
                    *(bf162*)(dh + 8 * CDIM) = h1;
                    *(bf162*)(dl + 8 * CDIM) = l1;
                } else {
                    bf16* vh = vt_hi + head * (size_t)CDIM * TDIM;
                    bf16* vl = vt_lo + head * (size_t)CDIM * TDIM;
                    vh[(size_t)(cc + 0) * TDIM + t] = h0.x;
                    vh[(size_t)(cc + 1) * TDIM + t] = h0.y;
                    vh[(size_t)(cc + 0) * TDIM + t + 8] = h1.x;
                    vh[(size_t)(cc + 1) * TDIM + t + 8] = h1.y;
                    vl[(size_t)(cc + 0) * TDIM + t] = l0.x;
                    vl[(size_t)(cc + 1) * TDIM + t] = l0.y;
                    vl[(size_t)(cc + 0) * TDIM + t + 8] = l1.x;
                    vl[(size_t)(cc + 1) * TDIM + t + 8] = l1.y;
                }
            } else if (MODE == 1) {
                float* p0 = g_s + z * (size_t)TDIM * TDIM + (size_t)r0 * TDIM + c0;
                *(float2*)p0 = make_float2(ac[0], ac[1]);
                *(float2*)(p0 + 8 * TDIM) = make_float2(ac[2], ac[3]);
            } else if (MODE == 2) {
                const int b = (int)z >> 2;
                const int h = (int)z & 3;
                bf162 h0, h1, l0, l1;
                split2(ac[0], h0.x, l0.x);
                split2(ac[1], h0.y, l0.y);
                split2(ac[2], h1.x, l1.x);
                split2(ac[3], h1.y, l1.y);
                const size_t off = ((size_t)(b * TDIM + r0)) * HC + h * CDIM + c0;
                *(bf162*)(a_hi + off) = h0;
                *(bf162*)(a_lo + off) = l0;
                *(bf162*)(a_hi + off + 8 * HC) = h1;
                *(bf162*)(a_lo + off + 8 * HC) = l1;
            } else {
                const float2 bi = *(const float2*)(bias + c0);
                float* p0 = OUT + (size_t)r0 * CDIM + c0;
                *(float2*)p0 = make_float2(ac[0] + bi.x, ac[1] + bi.y);
                *(float2*)(p0 + 8 * CDIM) = make_float2(ac[2] + bi.x, ac[3] + bi.y);
            }
        }
    }
}

// ---------------------------------------------------------------------------
// Row softmax over g_s -> (p_hi, p_lo). One block per row of 2048.
// ---------------------------------------------------------------------------
__global__ __launch_bounds__(256)
void softmax_k()
{
    const size_t row = blockIdx.x;
    const float* p = g_s + row * TDIM;
    bf16* ph = p_hi + row * TDIM;
    bf16* pl = p_lo + row * TDIM;
    const int tid = threadIdx.x;

    __shared__ float red[256];

    float v[8];
    float m = -1e30f;
#pragma unroll
    for (int i = 0; i < 8; i++) {
        v[i] = p[tid + i * 256];
        m = fmaxf(m, v[i]);
    }
    red[tid] = m;
    __syncthreads();
#pragma unroll
    for (int s = 128; s > 0; s >>= 1) {
        if (tid < s) red[tid] = fmaxf(red[tid], red[tid + s]);
        __syncthreads();
    }
    m = red[0];
    __syncthreads();

    float sum = 0.f;
#pragma unroll
    for (int i = 0; i < 8; i++) {
        v[i] = expf(v[i] - m);
        sum += v[i];
    }
    red[tid] = sum;
    __syncthreads();
#pragma unroll
    for (int s = 128; s > 0; s >>= 1) {
        if (tid < s) red[tid] += red[tid + s];
        __syncthreads();
    }
    const float inv = 1.f / red[0];
#pragma unroll
    for (int i = 0; i < 8; i++) {
        bf16 h, l;
        split2(v[i] * inv, h, l);
        ph[tid + i * 256] = h;
        pl[tid + i * 256] = l;
    }
}

// ---------------------------------------------------------------------------
// kernel_launch: 8 graph-capturable launches, no allocations.
// ---------------------------------------------------------------------------
extern "C" void kernel_launch(void* const* d_in, const int* in_sizes, int n_in,
                              void* d_out, int out_size)
{
    const float* x      = (const float*)d_in[0];
    const float* qkv_w  = (const float*)d_in[1];
    const float* proj_w = (const float*)d_in[2];
    const float* proj_b = (const float*)d_in[3];
    float* out = (float*)d_out;
    (void)in_sizes; (void)n_in; (void)out_size;

    cudaFuncSetAttribute(mgemm<0>, cudaFuncAttributeMaxDynamicSharedMemorySize, SMEM_BYTES);
    cudaFuncSetAttribute(mgemm<1>, cudaFuncAttributeMaxDynamicSharedMemorySize, SMEM_BYTES);
    cudaFuncSetAttribute(mgemm<2>, cudaFuncAttributeMaxDynamicSharedMemorySize, SMEM_BYTES);
    cudaFuncSetAttribute(mgemm<3>, cudaFuncAttributeMaxDynamicSharedMemorySize, SMEM_BYTES);

    // resolve device-global addresses for the split kernels
    bf16 *d_xs_hi, *d_xs_lo, *d_ws_hi, *d_ws_lo, *d_pws_hi, *d_pws_lo;
    cudaGetSymbolAddress((void**)&d_xs_hi,  xs_hi);
    cudaGetSymbolAddress((void**)&d_xs_lo,  xs_lo);
    cudaGetSymbolAddress((void**)&d_ws_hi,  ws_hi);
    cudaGetSymbolAddress((void**)&d_ws_lo,  ws_lo);
    cudaGetSymbolAddress((void**)&d_pws_hi, pws_hi);
    cudaGetSymbolAddress((void**)&d_pws_lo, pws_lo);

    dim3 blk(256);

    // 0) split inputs to bf16 hi/lo
    const size_t nx = (size_t)TOK * CDIM, nw = (size_t)QKVN * CDIM, np = (size_t)CDIM * HC;
    split_k<<<(unsigned)((nx / 4 + 255) / 256), blk>>>(x,      d_xs_hi,  d_xs_lo,  nx);
    split_k<<<(unsigned)((nw / 4 + 255) / 256), blk>>>(qkv_w,  d_ws_hi,  d_ws_lo,  nw);
    split_k<<<(unsigned)((np / 4 + 255) / 256), blk>>>(proj_w, d_pws_hi, d_pws_lo, np);

    // 1) QKV projection -> q (scaled), k, vt  (bf16 hi/lo)
    mgemm<0><<<dim3(QKVN / 128, TOK / 128, 1), blk, SMEM_BYTES>>>(nullptr, nullptr);
    // 2) S = Q K^T (scale pre-folded)
    mgemm<1><<<dim3(TDIM / 128, TDIM / 128, BH), blk, SMEM_BYTES>>>(nullptr, nullptr);
    // 3) softmax rows -> p hi/lo
    softmax_k<<<BH * TDIM, 256>>>();
    // 4) O = P V -> a hi/lo (proj-ready layout)
    mgemm<2><<<dim3(CDIM / 128, TDIM / 128, BH), blk, SMEM_BYTES>>>(nullptr, nullptr);
    // 5) final projection + bias -> out
    mgemm<3><<<dim3(CDIM / 128, TOK / 128, 1), blk, SMEM_BYTES>>>(out, proj_b);
}

// round 7
// speedup vs baseline: 2.6089x; 1.1462x over previous
#include <cuda_runtime.h>
#include <cuda_bf16.h>
#include <cstdint>

// ---------------------------------------------------------------------------
// Fixed problem shape
// ---------------------------------------------------------------------------
#define TDIM 2048
#define CDIM 512
#define BH   32            // B*H
#define TOK  16384         // B*T
#define QKVN 6144          // 3*H*C
#define HC   2048          // H*C
#define SCALE_F 0.08838834764831845f   // 1/sqrt(128)

typedef __nv_bfloat16 bf16;
typedef __nv_bfloat162 bf162;

// ---------------------------------------------------------------------------
// Scratch (static device arrays; no cudaMalloc allowed)
// All GEMM operands live as pre-split bf16 (hi, lo) pairs.
// ---------------------------------------------------------------------------
__device__ bf16 xs_hi [(size_t)TOK * CDIM];
__device__ bf16 xs_lo [(size_t)TOK * CDIM];
__device__ bf16 ws_hi [(size_t)QKVN * CDIM];
__device__ bf16 ws_lo [(size_t)QKVN * CDIM];
__device__ bf16 pws_hi[(size_t)CDIM * HC];
__device__ bf16 pws_lo[(size_t)CDIM * HC];

__device__ bf16 q_hi [(size_t)BH * TDIM * CDIM];   // [bh][t][c], SCALE folded in
__device__ bf16 q_lo [(size_t)BH * TDIM * CDIM];
__device__ bf16 k_hi [(size_t)BH * TDIM * CDIM];
__device__ bf16 k_lo [(size_t)BH * TDIM * CDIM];
__device__ bf16 vt_hi[(size_t)BH * CDIM * TDIM];   // [bh][c][t]
__device__ bf16 vt_lo[(size_t)BH * CDIM * TDIM];

__device__ float g_s [(size_t)BH * TDIM * TDIM];   // scores (scaled), fp32
__device__ bf16 p_hi [(size_t)BH * TDIM * TDIM];   // softmax(S)
__device__ bf16 p_lo [(size_t)BH * TDIM * TDIM];

__device__ bf16 a_hi [(size_t)TOK * HC];           // attn out, proj layout
__device__ bf16 a_lo [(size_t)TOK * HC];

// ---------------------------------------------------------------------------
// Smem: NS=2 stages x (A_hi | A_lo | B_hi | B_lo) tiles, rows padded to 40 bf16
// 80-byte rows: 16B-aligned for ldmatrix/cp.async, conflict-free ldsm phases.
// 2 stages -> 80 KB -> two CTAs co-resident per SM.
// ---------------------------------------------------------------------------
#define ROWPAD 40
#define TILE_BYTES (128 * ROWPAD * 2)     // 10240
#define STAGE_BYTES (4 * TILE_BYTES)      // 40960
#define NS 2
#define SMEM_BYTES (NS * STAGE_BYTES)     // 81920

#define OFF_AHI 0
#define OFF_ALO TILE_BYTES
#define OFF_BHI (2 * TILE_BYTES)
#define OFF_BLO (3 * TILE_BYTES)

// ---------------------------------------------------------------------------
// PTX helpers (base sm_80-class; no 'a'-suffix features)
// ---------------------------------------------------------------------------
__device__ __forceinline__ uint32_t smem_u32(const void* p) {
    uint32_t a;
    asm("{ .reg .u64 t; cvta.to.shared.u64 t, %1; cvt.u32.u64 %0, t; }" : "=r"(a) : "l"(p));
    return a;
}
__device__ __forceinline__ void cpa16(uint32_t dst, const void* src) {
    asm volatile("cp.async.ca.shared.global [%0], [%1], 16;" :: "r"(dst), "l"(src));
}
__device__ __forceinline__ void cp_commit() {
    asm volatile("cp.async.commit_group;" ::: "memory");
}
template <int N>
__device__ __forceinline__ void cp_wait() {
    asm volatile("cp.async.wait_group %0;" :: "n"(N) : "memory");
}
__device__ __forceinline__ void ldsm4(uint32_t* r, uint32_t addr) {
    asm volatile("ldmatrix.sync.aligned.m8n8.x4.shared.b16 {%0,%1,%2,%3}, [%4];"
                 : "=r"(r[0]), "=r"(r[1]), "=r"(r[2]), "=r"(r[3]) : "r"(addr));
}
__device__ __forceinline__ void ldsm2(uint32_t* r, uint32_t addr) {
    asm volatile("ldmatrix.sync.aligned.m8n8.x2.shared.b16 {%0,%1}, [%2];"
                 : "=r"(r[0]), "=r"(r[1]) : "r"(addr));
}
__device__ __forceinline__ void mma_bf16(float* c, const uint32_t* a, const uint32_t* b) {
    asm volatile("mma.sync.aligned.m16n8k16.row.col.f32.bf16.bf16.f32 "
                 "{%0,%1,%2,%3}, {%4,%5,%6,%7}, {%8,%9}, {%0,%1,%2,%3};"
                 : "+f"(c[0]), "+f"(c[1]), "+f"(c[2]), "+f"(c[3])
                 : "r"(a[0]), "r"(a[1]), "r"(a[2]), "r"(a[3]), "r"(b[0]), "r"(b[1]));
}
__device__ __forceinline__ void split2(float x, bf16& h, bf16& l) {
    h = __float2bfloat16_rn(x);
    l = __float2bfloat16_rn(x - __bfloat162float(h));
}

// ---------------------------------------------------------------------------
// Elementwise fp32 -> (hi, lo) bf16 splitter for kernel inputs
// ---------------------------------------------------------------------------
__global__ __launch_bounds__(256)
void split_k(const float* __restrict__ src, bf16* __restrict__ hi,
             bf16* __restrict__ lo, size_t n)
{
    size_t i = ((size_t)blockIdx.x * 256 + threadIdx.x) * 4;
    if (i >= n) return;
    float4 v = *(const float4*)(src + i);
    bf162 h0, h1, l0, l1;
    split2(v.x, h0.x, l0.x);
    split2(v.y, h0.y, l0.y);
    split2(v.z, h1.x, l1.x);
    split2(v.w, h1.y, l1.y);
    *(bf162*)(hi + i)     = h0;
    *(bf162*)(hi + i + 2) = h1;
    *(bf162*)(lo + i)     = l0;
    *(bf162*)(lo + i + 2) = l1;
}

// ---------------------------------------------------------------------------
// mma.sync bf16-split GEMM, cp.async 2-stage pipeline, 2 CTAs/SM. Modes:
//  MODE 0: QKV : xs[16384,512] @ ws[6144,512]^T -> q(,*SCALE)/k/vt hi+lo
//  MODE 1: S   : q[T,512] @ k[T,512]^T          -> g_s fp32  (z = head)
//  MODE 2: O   : p[T,T]  @ vt[512,2048]^T       -> a hi+lo   (z = head)
//  MODE 3: PROJ: a[16384,2048] @ pws[512,2048]^T + bias -> out fp32
// A, B row-major [rows, K] bf16 hi/lo. Tile 128x128, BK=32, 256 threads.
// ---------------------------------------------------------------------------
template <int MODE>
__global__ __launch_bounds__(256, 2)
void mgemm(float* __restrict__ OUT, const float* __restrict__ bias)
{
    constexpr int K = (MODE <= 1) ? CDIM : TDIM;   // MODE3 uses HC=2048=TDIM
    constexpr int NITER = K / 32;

    extern __shared__ char smc[];
    const uint32_t sb = smem_u32(smc);

    const int tid  = threadIdx.x;
    const int wid  = tid >> 5;
    const int lane = tid & 31;
    const int wm   = wid & 1;
    const int wn   = wid >> 1;
    const int m0   = blockIdx.y * 128;
    const int n0   = blockIdx.x * 128;
    const size_t z = blockIdx.z;

    const bf16 *Ah, *Al, *Bh, *Bl;
    if (MODE == 0)      { Ah = xs_hi;  Al = xs_lo;  Bh = ws_hi;  Bl = ws_lo; }
    else if (MODE == 1) {
        Ah = q_hi + z * (size_t)TDIM * CDIM; Al = q_lo + z * (size_t)TDIM * CDIM;
        Bh = k_hi + z * (size_t)TDIM * CDIM; Bl = k_lo + z * (size_t)TDIM * CDIM;
    } else if (MODE == 2) {
        Ah = p_hi + z * (size_t)TDIM * TDIM; Al = p_lo + z * (size_t)TDIM * TDIM;
        Bh = vt_hi + z * (size_t)CDIM * TDIM; Bl = vt_lo + z * (size_t)CDIM * TDIM;
    } else              { Ah = a_hi;  Al = a_lo;  Bh = pws_hi; Bl = pws_lo; }

    // loader geometry: r = row 0..127, hh = 0/16 (bf16 elems); 32B per (r,hh)
    const int lr = tid >> 1;
    const int lh = (tid & 1) * 16;
    const bf16* agh = Ah + (size_t)(m0 + lr) * K + lh;
    const bf16* agl = Al + (size_t)(m0 + lr) * K + lh;
    const bf16* bgh = Bh + (size_t)(n0 + lr) * K + lh;
    const bf16* bgl = Bl + (size_t)(n0 + lr) * K + lh;
    const uint32_t dstb = sb + (uint32_t)((lr * ROWPAD + lh) * 2);

#define ISSUE_STAGE(kt, buf) do {                                             \
        const int _k0 = (kt) * 32;                                            \
        const uint32_t _d = dstb + (uint32_t)((buf) * STAGE_BYTES);           \
        cpa16(_d + OFF_AHI,      agh + _k0);                                  \
        cpa16(_d + OFF_AHI + 16, agh + _k0 + 8);                              \
        cpa16(_d + OFF_ALO,      agl + _k0);                                  \
        cpa16(_d + OFF_ALO + 16, agl + _k0 + 8);                              \
        cpa16(_d + OFF_BHI,      bgh + _k0);                                  \
        cpa16(_d + OFF_BHI + 16, bgh + _k0 + 8);                              \
        cpa16(_d + OFF_BLO,      bgl + _k0);                                  \
        cpa16(_d + OFF_BLO + 16, bgl + _k0 + 8);                              \
    } while (0)

    float acc[4][4][4];
#pragma unroll
    for (int i = 0; i < 4; i++)
#pragma unroll
        for (int j = 0; j < 4; j++)
#pragma unroll
            for (int c = 0; c < 4; c++) acc[i][j][c] = 0.f;

    // prologue: stage 0
    ISSUE_STAGE(0, 0);
    cp_commit();

    for (int it = 0; it < NITER; ++it) {
        cp_wait<0>();               // stage `it` resident
        __syncthreads();            // all warps done reading stage it-1

        if (it + 1 < NITER) {       // refill the buffer consumed at it-1
            ISSUE_STAGE(it + 1, (it + 1) & 1);
            cp_commit();
        }

        const uint32_t stage = sb + (uint32_t)((it & 1) * STAGE_BYTES);
#pragma unroll
        for (int ks = 0; ks < 2; ks++) {
            uint32_t ah[4][4], al[4][4];
            const int arow = wm * 64 + (lane & 15);
            const int akoff = ks * 16 + (lane >> 4) * 8;
#pragma unroll
            for (int mt = 0; mt < 4; mt++) {
                const uint32_t ao = stage + (uint32_t)(((arow + mt * 16) * ROWPAD + akoff) * 2);
                ldsm4(ah[mt], ao + OFF_AHI);
                ldsm4(al[mt], ao + OFF_ALO);
            }
            const int brow = wn * 32 + (lane & 7);
            const int bkoff = ks * 16 + ((lane >> 3) & 1) * 8;
#pragma unroll
            for (int nt = 0; nt < 4; nt++) {
                uint32_t bh[2], bl[2];
                const uint32_t bo = stage + (uint32_t)(((brow + nt * 8) * ROWPAD + bkoff) * 2);
                ldsm2(bh, bo + OFF_BHI);
                ldsm2(bl, bo + OFF_BLO);
#pragma unroll
                for (int mt = 0; mt < 4; mt++) {
                    mma_bf16(acc[mt][nt], ah[mt], bh);
                    mma_bf16(acc[mt][nt], al[mt], bh);
                    mma_bf16(acc[mt][nt], ah[mt], bl);
                }
            }
        }
        __syncthreads();            // done reading stage it before it+2 overwrite
    }
#undef ISSUE_STAGE

    // ------------------------------------------------------------- epilogue
    const int g   = lane >> 2;
    const int tig = lane & 3;

#pragma unroll
    for (int mt = 0; mt < 4; mt++) {
#pragma unroll
        for (int nt = 0; nt < 4; nt++) {
            const int r0 = m0 + wm * 64 + mt * 16 + g;
            const int c0 = n0 + wn * 32 + nt * 8 + tig * 2;
            float* ac = acc[mt][nt];

            if (MODE == 0) {
                const int s = n0 >> 11;            // 0:q 1:k 2:v
                const int h = (n0 >> 9) & 3;
                const int cc = c0 & 511;
                const int b = m0 >> 11;
                const int t = r0 & 2047;
                const size_t head = (size_t)(b * 4 + h);
                const float sc = (s == 0) ? SCALE_F : 1.f;
                bf162 h0, h1, l0, l1;
                split2(ac[0] * sc, h0.x, l0.x);
                split2(ac[1] * sc, h0.y, l0.y);
                split2(ac[2] * sc, h1.x, l1.x);
                split2(ac[3] * sc, h1.y, l1.y);
                if (s < 2) {
                    bf16* dh = ((s == 0) ? q_hi : k_hi) + (head * TDIM + t) * CDIM + cc;
                    bf16* dl = ((s == 0) ? q_lo : k_lo) + (head * TDIM + t) * CDIM + cc;
                    *(bf162*)dh = h0;
                    *(bf162*)dl = l0;
                    *(bf162*)(dh + 8 * CDIM) = h1;
                    *(bf162*)(dl + 8 * CDIM) = l1;
                } else {
                    bf16* vh = vt_hi + head * (size_t)CDIM * TDIM;
                    bf16* vl = vt_lo + head * (size_t)CDIM * TDIM;
                    vh[(size_t)(cc + 0) * TDIM + t] = h0.x;
                    vh[(size_t)(cc + 1) * TDIM + t] = h0.y;
                    vh[(size_t)(cc + 0) * TDIM + t + 8] = h1.x;
                    vh[(size_t)(cc + 1) * TDIM + t + 8] = h1.y;
                    vl[(size_t)(cc + 0) * TDIM + t] = l0.x;
                    vl[(size_t)(cc + 1) * TDIM + t] = l0.y;
                    vl[(size_t)(cc + 0) * TDIM + t + 8] = l1.x;
                    vl[(size_t)(cc + 1) * TDIM + t + 8] = l1.y;
                }
            } else if (MODE == 1) {
                float* p0 = g_s + z * (size_t)TDIM * TDIM + (size_t)r0 * TDIM + c0;
                *(float2*)p0 = make_float2(ac[0], ac[1]);
                *(float2*)(p0 + 8 * TDIM) = make_float2(ac[2], ac[3]);
            } else if (MODE == 2) {
                const int b = (int)z >> 2;
                const int h = (int)z & 3;
                bf162 h0, h1, l0, l1;
                split2(ac[0], h0.x, l0.x);
                split2(ac[1], h0.y, l0.y);
                split2(ac[2], h1.x, l1.x);
                split2(ac[3], h1.y, l1.y);
                const size_t off = ((size_t)(b * TDIM + r0)) * HC + h * CDIM + c0;
                *(bf162*)(a_hi + off) = h0;
                *(bf162*)(a_lo + off) = l0;
                *(bf162*)(a_hi + off + 8 * HC) = h1;
                *(bf162*)(a_lo + off + 8 * HC) = l1;
            } else {
                const float2 bi = *(const float2*)(bias + c0);
                float* p0 = OUT + (size_t)r0 * CDIM + c0;
                *(float2*)p0 = make_float2(ac[0] + bi.x, ac[1] + bi.y);
                *(float2*)(p0 + 8 * CDIM) = make_float2(ac[2] + bi.x, ac[3] + bi.y);
            }
        }
    }
}

// ---------------------------------------------------------------------------
// Row softmax over g_s -> (p_hi, p_lo). One block per row of 2048.
// ---------------------------------------------------------------------------
__global__ __launch_bounds__(256)
void softmax_k()
{
    const size_t row = blockIdx.x;
    const float* p = g_s + row * TDIM;
    bf16* ph = p_hi + row * TDIM;
    bf16* pl = p_lo + row * TDIM;
    const int tid = threadIdx.x;

    __shared__ float red[256];

    float v[8];
    float m = -1e30f;
#pragma unroll
    for (int i = 0; i < 8; i++) {
        v[i] = p[tid + i * 256];
        m = fmaxf(m, v[i]);
    }
    red[tid] = m;
    __syncthreads();
#pragma unroll
    for (int s = 128; s > 0; s >>= 1) {
        if (tid < s) red[tid] = fmaxf(red[tid], red[tid + s]);
        __syncthreads();
    }
    m = red[0];
    __syncthreads();

    float sum = 0.f;
#pragma unroll
    for (int i = 0; i < 8; i++) {
        v[i] = expf(v[i] - m);
        sum += v[i];
    }
    red[tid] = sum;
    __syncthreads();
#pragma unroll
    for (int s = 128; s > 0; s >>= 1) {
        if (tid < s) red[tid] += red[tid + s];
        __syncthreads();
    }
    const float inv = 1.f / red[0];
#pragma unroll
    for (int i = 0; i < 8; i++) {
        bf16 h, l;
        split2(v[i] * inv, h, l);
        ph[tid + i * 256] = h;
        pl[tid + i * 256] = l;
    }
}

// ---------------------------------------------------------------------------
// kernel_launch: 8 graph-capturable launches, no allocations.
// ---------------------------------------------------------------------------
extern "C" void kernel_launch(void* const* d_in, const int* in_sizes, int n_in,
                              void* d_out, int out_size)
{
    const float* x      = (const float*)d_in[0];
    const float* qkv_w  = (const float*)d_in[1];
    const float* proj_w = (const float*)d_in[2];
    const float* proj_b = (const float*)d_in[3];
    float* out = (float*)d_out;
    (void)in_sizes; (void)n_in; (void)out_size;

    cudaFuncSetAttribute(mgemm<0>, cudaFuncAttributeMaxDynamicSharedMemorySize, SMEM_BYTES);
    cudaFuncSetAttribute(mgemm<1>, cudaFuncAttributeMaxDynamicSharedMemorySize, SMEM_BYTES);
    cudaFuncSetAttribute(mgemm<2>, cudaFuncAttributeMaxDynamicSharedMemorySize, SMEM_BYTES);
    cudaFuncSetAttribute(mgemm<3>, cudaFuncAttributeMaxDynamicSharedMemorySize, SMEM_BYTES);

    // resolve device-global addresses for the split kernels
    bf16 *d_xs_hi, *d_xs_lo, *d_ws_hi, *d_ws_lo, *d_pws_hi, *d_pws_lo;
    cudaGetSymbolAddress((void**)&d_xs_hi,  xs_hi);
    cudaGetSymbolAddress((void**)&d_xs_lo,  xs_lo);
    cudaGetSymbolAddress((void**)&d_ws_hi,  ws_hi);
    cudaGetSymbolAddress((void**)&d_ws_lo,  ws_lo);
    cudaGetSymbolAddress((void**)&d_pws_hi, pws_hi);
    cudaGetSymbolAddress((void**)&d_pws_lo, pws_lo);

    dim3 blk(256);

    // 0) split inputs to bf16 hi/lo
    const size_t nx = (size_t)TOK * CDIM, nw = (size_t)QKVN * CDIM, np = (size_t)CDIM * HC;
    split_k<<<(unsigned)((nx / 4 + 255) / 256), blk>>>(x,      d_xs_hi,  d_xs_lo,  nx);
    split_k<<<(unsigned)((nw / 4 + 255) / 256), blk>>>(qkv_w,  d_ws_hi,  d_ws_lo,  nw);
    split_k<<<(unsigned)((np / 4 + 255) / 256), blk>>>(proj_w, d_pws_hi, d_pws_lo, np);

    // 1) QKV projection -> q (scaled), k, vt  (bf16 hi/lo)
    mgemm<0><<<dim3(QKVN / 128, TOK / 128, 1), blk, SMEM_BYTES>>>(nullptr, nullptr);
    // 2) S = Q K^T (scale pre-folded)
    mgemm<1><<<dim3(TDIM / 128, TDIM / 128, BH), blk, SMEM_BYTES>>>(nullptr, nullptr);
    // 3) softmax rows -> p hi/lo
    softmax_k<<<BH * TDIM, 256>>>();
    // 4) O = P V -> a hi/lo (proj-ready layout)
    mgemm<2><<<dim3(CDIM / 128, TDIM / 128, BH), blk, SMEM_BYTES>>>(nullptr, nullptr);
    // 5) final projection + bias -> out
    mgemm<3><<<dim3(CDIM / 128, TOK / 128, 1), blk, SMEM_BYTES>>>(out, proj_b);
}

// round 9
// speedup vs baseline: 3.3968x; 1.3020x over previous
#include <cuda_runtime.h>
#include <cuda_fp16.h>
#include <cstdint>

// ---------------------------------------------------------------------------
// Fixed problem shape
// ---------------------------------------------------------------------------
#define TDIM 2048
#define CDIM 512
#define BH   32            // B*H
#define TOK  16384         // B*T
#define QKVN 6144          // 3*H*C
#define HC   2048          // H*C
#define SCALE_F 0.08838834764831845f   // 1/sqrt(128)

typedef __half fp16;

// ---------------------------------------------------------------------------
// Scratch (static device arrays; no cudaMalloc allowed)
// A-side operands: fp16 (hi, lo) pairs. B-side operands: single fp16.
// ---------------------------------------------------------------------------
__device__ fp16 xs_hi [(size_t)TOK * CDIM];
__device__ fp16 xs_lo [(size_t)TOK * CDIM];
__device__ fp16 ws_h  [(size_t)QKVN * CDIM];     // qkv_w, fp16
__device__ fp16 pws_h [(size_t)CDIM * HC];       // proj_w, fp16

__device__ fp16 q_hi [(size_t)BH * TDIM * CDIM]; // [bh][t][c], SCALE folded in
__device__ fp16 q_lo [(size_t)BH * TDIM * CDIM];
__device__ fp16 k_h  [(size_t)BH * TDIM * CDIM]; // [bh][t][c]
__device__ fp16 vt_h [(size_t)BH * CDIM * TDIM]; // [bh][c][t]

__device__ float g_s [(size_t)BH * TDIM * TDIM]; // scores (scaled), fp32
__device__ fp16 p_hi [(size_t)BH * TDIM * TDIM]; // softmax(S)
__device__ fp16 p_lo [(size_t)BH * TDIM * TDIM];

__device__ fp16 a_hi [(size_t)TOK * HC];         // attn out, proj layout
__device__ fp16 a_lo [(size_t)TOK * HC];

// ---------------------------------------------------------------------------
// Smem: NS=3 stages x (A_hi | A_lo | B_hi) tiles, rows padded to 40 fp16
// (80-byte rows: 16B-aligned for ldmatrix/cp.async, conflict-free ldsm)
// 3 stages x 30720B = 92160B -> 2 CTAs/SM (184320 < 228KB)
// ---------------------------------------------------------------------------
#define ROWPAD 40
#define TILE_BYTES (128 * ROWPAD * 2)     // 10240
#define STAGE_BYTES (3 * TILE_BYTES)      // 30720
#define NS 3
#define SMEM_BYTES (NS * STAGE_BYTES)     // 92160

#define OFF_AHI 0
#define OFF_ALO TILE_BYTES
#define OFF_BHI (2 * TILE_BYTES)

// ---------------------------------------------------------------------------
// PTX helpers (base sm_80-class; no 'a'-suffix features)
// ---------------------------------------------------------------------------
__device__ __forceinline__ uint32_t smem_u32(const void* p) {
    uint32_t a;
    asm("{ .reg .u64 t; cvta.to.shared.u64 t, %1; cvt.u32.u64 %0, t; }" : "=r"(a) : "l"(p));
    return a;
}
__device__ __forceinline__ void cpa16(uint32_t dst, const void* src) {
    asm volatile("cp.async.ca.shared.global [%0], [%1], 16;" :: "r"(dst), "l"(src));
}
__device__ __forceinline__ void cp_commit() {
    asm volatile("cp.async.commit_group;" ::: "memory");
}
template <int N>
__device__ __forceinline__ void cp_wait() {
    asm volatile("cp.async.wait_group %0;" :: "n"(N) : "memory");
}
__device__ __forceinline__ void ldsm4(uint32_t* r, uint32_t addr) {
    asm volatile("ldmatrix.sync.aligned.m8n8.x4.shared.b16 {%0,%1,%2,%3}, [%4];"
                 : "=r"(r[0]), "=r"(r[1]), "=r"(r[2]), "=r"(r[3]) : "r"(addr));
}
__device__ __forceinline__ void ldsm2(uint32_t* r, uint32_t addr) {
    asm volatile("ldmatrix.sync.aligned.m8n8.x2.shared.b16 {%0,%1}, [%2];"
                 : "=r"(r[0]), "=r"(r[1]) : "r"(addr));
}
__device__ __forceinline__ void mma_f16(float* c, const uint32_t* a, const uint32_t* b) {
    asm volatile("mma.sync.aligned.m16n8k16.row.col.f32.f16.f16.f32 "
                 "{%0,%1,%2,%3}, {%4,%5,%6,%7}, {%8,%9}, {%0,%1,%2,%3};"
                 : "+f"(c[0]), "+f"(c[1]), "+f"(c[2]), "+f"(c[3])
                 : "r"(a[0]), "r"(a[1]), "r"(a[2]), "r"(a[3]), "r"(b[0]), "r"(b[1]));
}
__device__ __forceinline__ void split2(float x, fp16& h, fp16& l) {
    h = __float2half_rn(x);
    l = __float2half_rn(x - __half2float(h));
}

// ---------------------------------------------------------------------------
// Elementwise fp32 -> (hi, lo) fp16 splitter
// ---------------------------------------------------------------------------
__global__ __launch_bounds__(256)
void split_k(const float* __restrict__ src, fp16* __restrict__ hi,
             fp16* __restrict__ lo, size_t n)
{
    size_t i = ((size_t)blockIdx.x * 256 + threadIdx.x) * 4;
    if (i >= n) return;
    float4 v = *(const float4*)(src + i);
    __half2 h0, h1, l0, l1;
    split2(v.x, h0.x, l0.x);
    split2(v.y, h0.y, l0.y);
    split2(v.z, h1.x, l1.x);
    split2(v.w, h1.y, l1.y);
    *(__half2*)(hi + i)     = h0;
    *(__half2*)(hi + i + 2) = h1;
    *(__half2*)(lo + i)     = l0;
    *(__half2*)(lo + i + 2) = l1;
}

// Elementwise fp32 -> fp16 cast (for B-side weights)
__global__ __launch_bounds__(256)
void cast_k(const float* __restrict__ src, fp16* __restrict__ dst, size_t n)
{
    size_t i = ((size_t)blockIdx.x * 256 + threadIdx.x) * 4;
    if (i >= n) return;
    float4 v = *(const float4*)(src + i);
    __half2 h0 = __floats2half2_rn(v.x, v.y);
    __half2 h1 = __floats2half2_rn(v.z, v.w);
    *(__half2*)(dst + i)     = h0;
    *(__half2*)(dst + i + 2) = h1;
}

// ---------------------------------------------------------------------------
// fp16 A-split 2-term GEMM, cp.async 3-stage pipeline, 2 CTAs/SM. Modes:
//  MODE 0: QKV : xs[16384,512] @ ws[6144,512]^T -> q(hi/lo,*SCALE)/k/vt
//  MODE 1: S   : q[T,512] @ k[T,512]^T          -> g_s fp32  (z = head)
//  MODE 2: O   : p[T,T]  @ vt[512,2048]^T       -> a hi/lo   (z = head)
//  MODE 3: PROJ: a[16384,2048] @ pws[512,2048]^T + bias -> out fp32
// A row-major [M,K] fp16 hi/lo; B row-major [N,K] fp16. Tile 128x128, BK=32.
// ---------------------------------------------------------------------------
template <int MODE>
__global__ __launch_bounds__(256, 2)
void mgemm(float* __restrict__ OUT, const float* __restrict__ bias)
{
    constexpr int K = (MODE <= 1) ? CDIM : TDIM;   // MODE3 uses HC=2048=TDIM
    constexpr int NITER = K / 32;

    extern __shared__ char smc[];
    const uint32_t sb = smem_u32(smc);

    const int tid  = threadIdx.x;
    const int wid  = tid >> 5;
    const int lane = tid & 31;
    const int wm   = wid & 1;
    const int wn   = wid >> 1;
    const int m0   = blockIdx.y * 128;
    const int n0   = blockIdx.x * 128;
    const size_t z = blockIdx.z;

    const fp16 *Ah, *Al, *Bh;
    if (MODE == 0)      { Ah = xs_hi;  Al = xs_lo;  Bh = ws_h; }
    else if (MODE == 1) {
        Ah = q_hi + z * (size_t)TDIM * CDIM; Al = q_lo + z * (size_t)TDIM * CDIM;
        Bh = k_h + z * (size_t)TDIM * CDIM;
    } else if (MODE == 2) {
        Ah = p_hi + z * (size_t)TDIM * TDIM; Al = p_lo + z * (size_t)TDIM * TDIM;
        Bh = vt_h + z * (size_t)CDIM * TDIM;
    } else              { Ah = a_hi;  Al = a_lo;  Bh = pws_h; }

    // loader geometry: r = row 0..127, lh = 0/16 (fp16 elems); 32B per (r,lh)
    const int lr = tid >> 1;
    const int lh = (tid & 1) * 16;
    const fp16* agh = Ah + (size_t)(m0 + lr) * K + lh;
    const fp16* agl = Al + (size_t)(m0 + lr) * K + lh;
    const fp16* bgh = Bh + (size_t)(n0 + lr) * K + lh;
    const uint32_t dstb = sb + (uint32_t)((lr * ROWPAD + lh) * 2);

#define ISSUE_STAGE(kt, buf) do {                                             \
        const int _k0 = (kt) * 32;                                            \
        const uint32_t _d = dstb + (uint32_t)((buf) * STAGE_BYTES);           \
        cpa16(_d + OFF_AHI,      agh + _k0);                                  \
        cpa16(_d + OFF_AHI + 16, agh + _k0 + 8);                              \
        cpa16(_d + OFF_ALO,      agl + _k0);                                  \
        cpa16(_d + OFF_ALO + 16, agl + _k0 + 8);                              \
        cpa16(_d + OFF_BHI,      bgh + _k0);                                  \
        cpa16(_d + OFF_BHI + 16, bgh + _k0 + 8);                              \
    } while (0)

    float acc[4][4][4];
#pragma unroll
    for (int i = 0; i < 4; i++)
#pragma unroll
        for (int j = 0; j < 4; j++)
#pragma unroll
            for (int c = 0; c < 4; c++) acc[i][j][c] = 0.f;

    // prologue: stages 0, 1
    ISSUE_STAGE(0, 0);
    cp_commit();
    ISSUE_STAGE(1, 1);
    cp_commit();

    for (int it = 0; it < NITER; ++it) {
        cp_wait<1>();               // stage `it` resident (<=1 group in flight)
        __syncthreads();            // all warps past MMA of it-1; safe to refill

        if (it + 2 < NITER) {
            ISSUE_STAGE(it + 2, (it + 2) % NS);
            cp_commit();
        }

        const uint32_t stage = sb + (uint32_t)((it % NS) * STAGE_BYTES);
#pragma unroll
        for (int ks = 0; ks < 2; ks++) {
            uint32_t ah[4][4], al[4][4];
            const int arow = wm * 64 + (lane & 15);
            const int akoff = ks * 16 + (lane >> 4) * 8;
#pragma unroll
            for (int mt = 0; mt < 4; mt++) {
                const uint32_t ao = stage + (uint32_t)(((arow + mt * 16) * ROWPAD + akoff) * 2);
                ldsm4(ah[mt], ao + OFF_AHI);
                ldsm4(al[mt], ao + OFF_ALO);
            }
            const int brow = wn * 32 + (lane & 7);
            const int bkoff = ks * 16 + ((lane >> 3) & 1) * 8;
#pragma unroll
            for (int nt = 0; nt < 4; nt++) {
                uint32_t bh[2];
                const uint32_t bo = stage + (uint32_t)(((brow + nt * 8) * ROWPAD + bkoff) * 2);
                ldsm2(bh, bo + OFF_BHI);
#pragma unroll
                for (int mt = 0; mt < 4; mt++) {
                    mma_f16(acc[mt][nt], ah[mt], bh);
                    mma_f16(acc[mt][nt], al[mt], bh);
                }
            }
        }
    }
#undef ISSUE_STAGE

    // ------------------------------------------------------------- epilogue
    const int g   = lane >> 2;
    const int tig = lane & 3;

#pragma unroll
    for (int mt = 0; mt < 4; mt++) {
#pragma unroll
        for (int nt = 0; nt < 4; nt++) {
            const int r0 = m0 + wm * 64 + mt * 16 + g;
            const int c0 = n0 + wn * 32 + nt * 8 + tig * 2;
            float* ac = acc[mt][nt];

            if (MODE == 0) {
                const int s = n0 >> 11;            // 0:q 1:k 2:v
                const int h = (n0 >> 9) & 3;
                const int cc = c0 & 511;
                const int b = m0 >> 11;
                const int t = r0 & 2047;
                const size_t head = (size_t)(b * 4 + h);
                if (s == 0) {                      // q: scaled hi/lo
                    __half2 h0, h1, l0, l1;
                    split2(ac[0] * SCALE_F, h0.x, l0.x);
                    split2(ac[1] * SCALE_F, h0.y, l0.y);
                    split2(ac[2] * SCALE_F, h1.x, l1.x);
                    split2(ac[3] * SCALE_F, h1.y, l1.y);
                    fp16* dh = q_hi + (head * TDIM + t) * CDIM + cc;
                    fp16* dl = q_lo + (head * TDIM + t) * CDIM + cc;
                    *(__half2*)dh = h0;
                    *(__half2*)dl = l0;
                    *(__half2*)(dh + 8 * CDIM) = h1;
                    *(__half2*)(dl + 8 * CDIM) = l1;
                } else if (s == 1) {               // k: single fp16
                    fp16* dh = k_h + (head * TDIM + t) * CDIM + cc;
                    *(__half2*)dh = __floats2half2_rn(ac[0], ac[1]);
                    *(__half2*)(dh + 8 * CDIM) = __floats2half2_rn(ac[2], ac[3]);
                } else {                           // v: transposed single fp16
                    fp16* vb = vt_h + head * (size_t)CDIM * TDIM;
                    vb[(size_t)(cc + 0) * TDIM + t]     = __float2half_rn(ac[0]);
                    vb[(size_t)(cc + 1) * TDIM + t]     = __float2half_rn(ac[1]);
                    vb[(size_t)(cc + 0) * TDIM + t + 8] = __float2half_rn(ac[2]);
                    vb[(size_t)(cc + 1) * TDIM + t + 8] = __float2half_rn(ac[3]);
                }
            } else if (MODE == 1) {
                float* p0 = g_s + z * (size_t)TDIM * TDIM + (size_t)r0 * TDIM + c0;
                *(float2*)p0 = make_float2(ac[0], ac[1]);
                *(float2*)(p0 + 8 * TDIM) = make_float2(ac[2], ac[3]);
            } else if (MODE == 2) {
                const int b = (int)z >> 2;
                const int h = (int)z & 3;
                __half2 h0, h1, l0, l1;
                split2(ac[0], h0.x, l0.x);
                split2(ac[1], h0.y, l0.y);
                split2(ac[2], h1.x, l1.x);
                split2(ac[3], h1.y, l1.y);
                const size_t off = ((size_t)(b * TDIM + r0)) * HC + h * CDIM + c0;
                *(__half2*)(a_hi + off) = h0;
                *(__half2*)(a_lo + off) = l0;
                *(__half2*)(a_hi + off + 8 * HC) = h1;
                *(__half2*)(a_lo + off + 8 * HC) = l1;
            } else {
                const float2 bi = *(const float2*)(bias + c0);
                float* p0 = OUT + (size_t)r0 * CDIM + c0;
                *(float2*)p0 = make_float2(ac[0] + bi.x, ac[1] + bi.y);
                *(float2*)(p0 + 8 * CDIM) = make_float2(ac[2] + bi.x, ac[3] + bi.y);
            }
        }
    }
}

// ---------------------------------------------------------------------------
// Row softmax over g_s -> (p_hi, p_lo). One block per row of 2048.
// ---------------------------------------------------------------------------
__global__ __launch_bounds__(256)
void softmax_k()
{
    const size_t row = blockIdx.x;
    const float* p = g_s + row * TDIM;
    fp16* ph = p_hi + row * TDIM;
    fp16* pl = p_lo + row * TDIM;
    const int tid = threadIdx.x;

    __shared__ float red[256];

    float v[8];
    float m = -1e30f;
#pragma unroll
    for (int i = 0; i < 8; i++) {
        v[i] = p[tid + i * 256];
        m = fmaxf(m, v[i]);
    }
    red[tid] = m;
    __syncthreads();
#pragma unroll
    for (int s = 128; s > 0; s >>= 1) {
        if (tid < s) red[tid] = fmaxf(red[tid], red[tid + s]);
        __syncthreads();
    }
    m = red[0];
    __syncthreads();

    float sum = 0.f;
#pragma unroll
    for (int i = 0; i < 8; i++) {
        v[i] = expf(v[i] - m);
        sum += v[i];
    }
    red[tid] = sum;
    __syncthreads();
#pragma unroll
    for (int s = 128; s > 0; s >>= 1) {
        if (tid < s) red[tid] += red[tid + s];
        __syncthreads();
    }
    const float inv = 1.f / red[0];
#pragma unroll
    for (int i = 0; i < 8; i++) {
        fp16 h, l;
        split2(v[i] * inv, h, l);
        ph[tid + i * 256] = h;
        pl[tid + i * 256] = l;
    }
}

// ---------------------------------------------------------------------------
// kernel_launch: graph-capturable launches, no allocations.
// ---------------------------------------------------------------------------
extern "C" void kernel_launch(void* const* d_in, const int* in_sizes, int n_in,
                              void* d_out, int out_size)
{
    const float* x      = (const float*)d_in[0];
    const float* qkv_w  = (const float*)d_in[1];
    const float* proj_w = (const float*)d_in[2];
    const float* proj_b = (const float*)d_in[3];
    float* out = (float*)d_out;
    (void)in_sizes; (void)n_in; (void)out_size;

    cudaFuncSetAttribute(mgemm<0>, cudaFuncAttributeMaxDynamicSharedMemorySize, SMEM_BYTES);
    cudaFuncSetAttribute(mgemm<1>, cudaFuncAttributeMaxDynamicSharedMemorySize, SMEM_BYTES);
    cudaFuncSetAttribute(mgemm<2>, cudaFuncAttributeMaxDynamicSharedMemorySize, SMEM_BYTES);
    cudaFuncSetAttribute(mgemm<3>, cudaFuncAttributeMaxDynamicSharedMemorySize, SMEM_BYTES);

    fp16 *d_xs_hi, *d_xs_lo, *d_ws, *d_pws;
    cudaGetSymbolAddress((void**)&d_xs_hi, xs_hi);
    cudaGetSymbolAddress((void**)&d_xs_lo, xs_lo);
    cudaGetSymbolAddress((void**)&d_ws,    ws_h);
    cudaGetSymbolAddress((void**)&d_pws,   pws_h);

    dim3 blk(256);

    // 0) prepare operands: x -> hi/lo split; weights -> fp16 cast
    const size_t nx = (size_t)TOK * CDIM, nw = (size_t)QKVN * CDIM, np = (size_t)CDIM * HC;
    split_k<<<(unsigned)((nx / 4 + 255) / 256), blk>>>(x, d_xs_hi, d_xs_lo, nx);
    cast_k <<<(unsigned)((nw / 4 + 255) / 256), blk>>>(qkv_w,  d_ws,  nw);
    cast_k <<<(unsigned)((np / 4 + 255) / 256), blk>>>(proj_w, d_pws, np);

    // 1) QKV projection -> q (scaled hi/lo), k, vt
    mgemm<0><<<dim3(QKVN / 128, TOK / 128, 1), blk, SMEM_BYTES>>>(nullptr, nullptr);
    // 2) S = Q K^T (scale pre-folded)
    mgemm<1><<<dim3(TDIM / 128, TDIM / 128, BH), blk, SMEM_BYTES>>>(nullptr, nullptr);
    // 3) softmax rows -> p hi/lo
    softmax_k<<<BH * TDIM, 256>>>();
    // 4) O = P V -> a hi/lo (proj-ready layout)
    mgemm<2><<<dim3(CDIM / 128, TDIM / 128, BH), blk, SMEM_BYTES>>>(nullptr, nullptr);
    // 5) final projection + bias -> out
    mgemm<3><<<dim3(CDIM / 128, TOK / 128, 1), blk, SMEM_BYTES>>>(out, proj_b);
}

// round 10
// speedup vs baseline: 3.7057x; 1.0909x over previous
#include <cuda_runtime.h>
#include <cuda_fp16.h>
#include <cstdint>

// ---------------------------------------------------------------------------
// Fixed problem shape
// ---------------------------------------------------------------------------
#define TDIM 2048
#define CDIM 512
#define BH   32            // B*H
#define TOK  16384         // B*T
#define QKVN 6144          // 3*H*C
#define HC   2048          // H*C
#define SCALE_F 0.08838834764831845f   // 1/sqrt(128)

typedef __half fp16;

// ---------------------------------------------------------------------------
// Scratch (static device arrays; no cudaMalloc allowed)
// A-side operands: fp16 (hi, lo) pairs. B-side operands: single fp16.
// ---------------------------------------------------------------------------
__device__ fp16 xs_hi [(size_t)TOK * CDIM];
__device__ fp16 xs_lo [(size_t)TOK * CDIM];
__device__ fp16 ws_h  [(size_t)QKVN * CDIM];     // qkv_w, fp16
__device__ fp16 pws_h [(size_t)CDIM * HC];       // proj_w, fp16

__device__ fp16 q_hi [(size_t)BH * TDIM * CDIM]; // [bh][t][c], SCALE folded in
__device__ fp16 q_lo [(size_t)BH * TDIM * CDIM];
__device__ fp16 k_h  [(size_t)BH * TDIM * CDIM]; // [bh][t][c]
__device__ fp16 vt_h [(size_t)BH * CDIM * TDIM]; // [bh][c][t]

__device__ float g_s [(size_t)BH * TDIM * TDIM]; // scores (scaled), fp32
__device__ fp16 p_hi [(size_t)BH * TDIM * TDIM]; // softmax(S)
__device__ fp16 p_lo [(size_t)BH * TDIM * TDIM];

__device__ fp16 a_hi [(size_t)TOK * HC];         // attn out, proj layout
__device__ fp16 a_lo [(size_t)TOK * HC];

// ---------------------------------------------------------------------------
// Smem: NS=3 stages x (A_hi | A_lo | B_hi) tiles, rows padded to 40 fp16
// 3 stages x 30720B = 92160B -> 2 CTAs/SM
// ---------------------------------------------------------------------------
#define ROWPAD 40
#define TILE_BYTES (128 * ROWPAD * 2)     // 10240
#define STAGE_BYTES (3 * TILE_BYTES)      // 30720
#define NS 3
#define SMEM_BYTES (NS * STAGE_BYTES)     // 92160

#define OFF_AHI 0
#define OFF_ALO TILE_BYTES
#define OFF_BHI (2 * TILE_BYTES)

// ---------------------------------------------------------------------------
// PTX helpers (base sm_80-class; no 'a'-suffix features)
// ---------------------------------------------------------------------------
__device__ __forceinline__ uint32_t smem_u32(const void* p) {
    uint32_t a;
    asm("{ .reg .u64 t; cvta.to.shared.u64 t, %1; cvt.u32.u64 %0, t; }" : "=r"(a) : "l"(p));
    return a;
}
__device__ __forceinline__ void cpa16(uint32_t dst, const void* src) {
    asm volatile("cp.async.ca.shared.global [%0], [%1], 16;" :: "r"(dst), "l"(src));
}
__device__ __forceinline__ void cp_commit() {
    asm volatile("cp.async.commit_group;" ::: "memory");
}
template <int N>
__device__ __forceinline__ void cp_wait() {
    asm volatile("cp.async.wait_group %0;" :: "n"(N) : "memory");
}
__device__ __forceinline__ void ldsm4(uint32_t* r, uint32_t addr) {
    asm volatile("ldmatrix.sync.aligned.m8n8.x4.shared.b16 {%0,%1,%2,%3}, [%4];"
                 : "=r"(r[0]), "=r"(r[1]), "=r"(r[2]), "=r"(r[3]) : "r"(addr));
}
__device__ __forceinline__ void mma_f16(float* c, const uint32_t* a, const uint32_t* b) {
    asm volatile("mma.sync.aligned.m16n8k16.row.col.f32.f16.f16.f32 "
                 "{%0,%1,%2,%3}, {%4,%5,%6,%7}, {%8,%9}, {%0,%1,%2,%3};"
                 : "+f"(c[0]), "+f"(c[1]), "+f"(c[2]), "+f"(c[3])
                 : "r"(a[0]), "r"(a[1]), "r"(a[2]), "r"(a[3]), "r"(b[0]), "r"(b[1]));
}
__device__ __forceinline__ void split2(float x, fp16& h, fp16& l) {
    h = __float2half_rn(x);
    l = __float2half_rn(x - __half2float(h));
}

// ---------------------------------------------------------------------------
// Elementwise fp32 -> (hi, lo) fp16 splitter
// ---------------------------------------------------------------------------
__global__ __launch_bounds__(256)
void split_k(const float* __restrict__ src, fp16* __restrict__ hi,
             fp16* __restrict__ lo, size_t n)
{
    size_t i = ((size_t)blockIdx.x * 256 + threadIdx.x) * 4;
    if (i >= n) return;
    float4 v = *(const float4*)(src + i);
    __half2 h0, h1, l0, l1;
    split2(v.x, h0.x, l0.x);
    split2(v.y, h0.y, l0.y);
    split2(v.z, h1.x, l1.x);
    split2(v.w, h1.y, l1.y);
    *(__half2*)(hi + i)     = h0;
    *(__half2*)(hi + i + 2) = h1;
    *(__half2*)(lo + i)     = l0;
    *(__half2*)(lo + i + 2) = l1;
}

// Elementwise fp32 -> fp16 cast (for B-side weights)
__global__ __launch_bounds__(256)
void cast_k(const float* __restrict__ src, fp16* __restrict__ dst, size_t n)
{
    size_t i = ((size_t)blockIdx.x * 256 + threadIdx.x) * 4;
    if (i >= n) return;
    float4 v = *(const float4*)(src + i);
    __half2 h0 = __floats2half2_rn(v.x, v.y);
    __half2 h1 = __floats2half2_rn(v.z, v.w);
    *(__half2*)(dst + i)     = h0;
    *(__half2*)(dst + i + 2) = h1;
}

// ---------------------------------------------------------------------------
// fp16 A-split 2-term GEMM, cp.async 3-stage pipeline, 2 CTAs/SM. Modes:
//  MODE 0: QKV : xs[16384,512] @ ws[6144,512]^T -> q(hi/lo,*SCALE)/k/vt
//  MODE 1: S   : q[T,512] @ k[T,512]^T          -> g_s fp32  (z = head)
//  MODE 2: O   : p[T,T]  @ vt[512,2048]^T       -> a hi/lo   (z = head)
//  MODE 3: PROJ: a[16384,2048] @ pws[512,2048]^T + bias -> out fp32
// Warp layout 4x2 (warp tile 32m x 64n); B fragments via x4 ldmatrix pairs.
// ---------------------------------------------------------------------------
template <int MODE>
__global__ __launch_bounds__(256, 2)
void mgemm(float* __restrict__ OUT, const float* __restrict__ bias)
{
    constexpr int K = (MODE <= 1) ? CDIM : TDIM;   // MODE3 uses HC=2048=TDIM
    constexpr int NITER = K / 32;

    extern __shared__ char smc[];
    const uint32_t sb = smem_u32(smc);

    const int tid  = threadIdx.x;
    const int wid  = tid >> 5;
    const int lane = tid & 31;
    const int wm   = wid & 3;       // 0..3 -> m offset *32
    const int wn   = wid >> 2;      // 0..1 -> n offset *64
    const int m0   = blockIdx.y * 128;
    const int n0   = blockIdx.x * 128;
    const size_t z = blockIdx.z;

    const fp16 *Ah, *Al, *Bh;
    if (MODE == 0)      { Ah = xs_hi;  Al = xs_lo;  Bh = ws_h; }
    else if (MODE == 1) {
        Ah = q_hi + z * (size_t)TDIM * CDIM; Al = q_lo + z * (size_t)TDIM * CDIM;
        Bh = k_h + z * (size_t)TDIM * CDIM;
    } else if (MODE == 2) {
        Ah = p_hi + z * (size_t)TDIM * TDIM; Al = p_lo + z * (size_t)TDIM * TDIM;
        Bh = vt_h + z * (size_t)CDIM * TDIM;
    } else              { Ah = a_hi;  Al = a_lo;  Bh = pws_h; }

    // loader geometry: r = row 0..127, lh = 0/16 (fp16 elems); 32B per (r,lh)
    const int lr = tid >> 1;
    const int lh = (tid & 1) * 16;
    const fp16* agh = Ah + (size_t)(m0 + lr) * K + lh;
    const fp16* agl = Al + (size_t)(m0 + lr) * K + lh;
    const fp16* bgh = Bh + (size_t)(n0 + lr) * K + lh;
    const uint32_t dstb = sb + (uint32_t)((lr * ROWPAD + lh) * 2);

#define ISSUE_STAGE(kt, buf) do {                                             \
        const int _k0 = (kt) * 32;                                            \
        const uint32_t _d = dstb + (uint32_t)((buf) * STAGE_BYTES);           \
        cpa16(_d + OFF_AHI,      agh + _k0);                                  \
        cpa16(_d + OFF_AHI + 16, agh + _k0 + 8);                              \
        cpa16(_d + OFF_ALO,      agl + _k0);                                  \
        cpa16(_d + OFF_ALO + 16, agl + _k0 + 8);                              \
        cpa16(_d + OFF_BHI,      bgh + _k0);                                  \
        cpa16(_d + OFF_BHI + 16, bgh + _k0 + 8);                              \
    } while (0)

    float acc[2][8][4];
#pragma unroll
    for (int i = 0; i < 2; i++)
#pragma unroll
        for (int j = 0; j < 8; j++)
#pragma unroll
            for (int c = 0; c < 4; c++) acc[i][j][c] = 0.f;

    // prologue: stages 0, 1
    ISSUE_STAGE(0, 0);
    cp_commit();
    ISSUE_STAGE(1, 1);
    cp_commit();

    for (int it = 0; it < NITER; ++it) {
        cp_wait<1>();               // stage `it` resident (<=1 group in flight)
        __syncthreads();            // all warps past MMA of it-1; safe to refill

        if (it + 2 < NITER) {
            ISSUE_STAGE(it + 2, (it + 2) % NS);
            cp_commit();
        }

        const uint32_t stage = sb + (uint32_t)((it % NS) * STAGE_BYTES);
#pragma unroll
        for (int ks = 0; ks < 2; ks++) {
            // A fragments: 2 m-tiles x (hi, lo); 16m x 16k each (ldsm x4)
            uint32_t ah[2][4], al[2][4];
            const int arow  = wm * 32 + (lane & 15);
            const int akoff = ks * 16 + (lane >> 4) * 8;
#pragma unroll
            for (int mt = 0; mt < 2; mt++) {
                const uint32_t ao = stage + (uint32_t)(((arow + mt * 16) * ROWPAD + akoff) * 2);
                ldsm4(ah[mt], ao + OFF_AHI);
                ldsm4(al[mt], ao + OFF_ALO);
            }
            // B fragments: 8 n-tiles as 4 x4-ldmatrix pairs (16n x 16k each)
            uint32_t bq[8][2];
            const int brow  = wn * 64 + (lane & 7) + ((lane >> 4) & 1) * 8;
            const int bkoff = ks * 16 + ((lane >> 3) & 1) * 8;
#pragma unroll
            for (int pr = 0; pr < 4; pr++) {
                uint32_t r4[4];
                const uint32_t bo = stage + (uint32_t)(((brow + pr * 16) * ROWPAD + bkoff) * 2);
                ldsm4(r4, bo + OFF_BHI);
                bq[pr * 2 + 0][0] = r4[0];
                bq[pr * 2 + 0][1] = r4[1];
                bq[pr * 2 + 1][0] = r4[2];
                bq[pr * 2 + 1][1] = r4[3];
            }
#pragma unroll
            for (int nt = 0; nt < 8; nt++) {
#pragma unroll
                for (int mt = 0; mt < 2; mt++) {
                    mma_f16(acc[mt][nt], ah[mt], bq[nt]);
                    mma_f16(acc[mt][nt], al[mt], bq[nt]);
                }
            }
        }
    }
#undef ISSUE_STAGE

    // ------------------------------------------------------------- epilogue
    const int g   = lane >> 2;
    const int tig = lane & 3;

#pragma unroll
    for (int mt = 0; mt < 2; mt++) {
#pragma unroll
        for (int nt = 0; nt < 8; nt++) {
            const int r0 = m0 + wm * 32 + mt * 16 + g;
            const int c0 = n0 + wn * 64 + nt * 8 + tig * 2;
            float* ac = acc[mt][nt];

            if (MODE == 0) {
                const int s = n0 >> 11;            // 0:q 1:k 2:v
                const int h = (n0 >> 9) & 3;
                const int cc = c0 & 511;
                const int b = m0 >> 11;
                const int t = r0 & 2047;
                const size_t head = (size_t)(b * 4 + h);
                if (s == 0) {                      // q: scaled hi/lo
                    __half2 h0, h1, l0, l1;
                    split2(ac[0] * SCALE_F, h0.x, l0.x);
                    split2(ac[1] * SCALE_F, h0.y, l0.y);
                    split2(ac[2] * SCALE_F, h1.x, l1.x);
                    split2(ac[3] * SCALE_F, h1.y, l1.y);
                    fp16* dh = q_hi + (head * TDIM + t) * CDIM + cc;
                    fp16* dl = q_lo + (head * TDIM + t) * CDIM + cc;
                    *(__half2*)dh = h0;
                    *(__half2*)dl = l0;
                    *(__half2*)(dh + 8 * CDIM) = h1;
                    *(__half2*)(dl + 8 * CDIM) = l1;
                } else if (s == 1) {               // k: single fp16
                    fp16* dh = k_h + (head * TDIM + t) * CDIM + cc;
                    *(__half2*)dh = __floats2half2_rn(ac[0], ac[1]);
                    *(__half2*)(dh + 8 * CDIM) = __floats2half2_rn(ac[2], ac[3]);
                } else {                           // v: transposed single fp16
                    fp16* vb = vt_h + head * (size_t)CDIM * TDIM;
                    vb[(size_t)(cc + 0) * TDIM + t]     = __float2half_rn(ac[0]);
                    vb[(size_t)(cc + 1) * TDIM + t]     = __float2half_rn(ac[1]);
                    vb[(size_t)(cc + 0) * TDIM + t + 8] = __float2half_rn(ac[2]);
                    vb[(size_t)(cc + 1) * TDIM + t + 8] = __float2half_rn(ac[3]);
                }
            } else if (MODE == 1) {
                float* p0 = g_s + z * (size_t)TDIM * TDIM + (size_t)r0 * TDIM + c0;
                *(float2*)p0 = make_float2(ac[0], ac[1]);
                *(float2*)(p0 + 8 * TDIM) = make_float2(ac[2], ac[3]);
            } else if (MODE == 2) {
                const int b = (int)z >> 2;
                const int h = (int)z & 3;
                __half2 h0, h1, l0, l1;
                split2(ac[0], h0.x, l0.x);
                split2(ac[1], h0.y, l0.y);
                split2(ac[2], h1.x, l1.x);
                split2(ac[3], h1.y, l1.y);
                const size_t off = ((size_t)(b * TDIM + r0)) * HC + h * CDIM + c0;
                *(__half2*)(a_hi + off) = h0;
                *(__half2*)(a_lo + off) = l0;
                *(__half2*)(a_hi + off + 8 * HC) = h1;
                *(__half2*)(a_lo + off + 8 * HC) = l1;
            } else {
                const float2 bi = *(const float2*)(bias + c0);
                float* p0 = OUT + (size_t)r0 * CDIM + c0;
                *(float2*)p0 = make_float2(ac[0] + bi.x, ac[1] + bi.y);
                *(float2*)(p0 + 8 * CDIM) = make_float2(ac[2] + bi.x, ac[3] + bi.y);
            }
        }
    }
}

// ---------------------------------------------------------------------------
// Row softmax over g_s -> (p_hi, p_lo). One block per row of 2048.
// ---------------------------------------------------------------------------
__global__ __launch_bounds__(256)
void softmax_k()
{
    const size_t row = blockIdx.x;
    const float* p = g_s + row * TDIM;
    fp16* ph = p_hi + row * TDIM;
    fp16* pl = p_lo + row * TDIM;
    const int tid = threadIdx.x;

    __shared__ float red[256];

    float v[8];
    float m = -1e30f;
#pragma unroll
    for (int i = 0; i < 8; i++) {
        v[i] = p[tid + i * 256];
        m = fmaxf(m, v[i]);
    }
    red[tid] = m;
    __syncthreads();
#pragma unroll
    for (int s = 128; s > 0; s >>= 1) {
        if (tid < s) red[tid] = fmaxf(red[tid], red[tid + s]);
        __syncthreads();
    }
    m = red[0];
    __syncthreads();

    float sum = 0.f;
#pragma unroll
    for (int i = 0; i < 8; i++) {
        v[i] = expf(v[i] - m);
        sum += v[i];
    }
    red[tid] = sum;
    __syncthreads();
#pragma unroll
    for (int s = 128; s > 0; s >>= 1) {
        if (tid < s) red[tid] += red[tid + s];
        __syncthreads();
    }
    const float inv = 1.f / red[0];
#pragma unroll
    for (int i = 0; i < 8; i++) {
        fp16 h, l;
        split2(v[i] * inv, h, l);
        ph[tid + i * 256] = h;
        pl[tid + i * 256] = l;
    }
}

// ---------------------------------------------------------------------------
// kernel_launch: graph-capturable launches, no allocations.
// ---------------------------------------------------------------------------
extern "C" void kernel_launch(void* const* d_in, const int* in_sizes, int n_in,
                              void* d_out, int out_size)
{
    const float* x      = (const float*)d_in[0];
    const float* qkv_w  = (const float*)d_in[1];
    const float* proj_w = (const float*)d_in[2];
    const float* proj_b = (const float*)d_in[3];
    float* out = (float*)d_out;
    (void)in_sizes; (void)n_in; (void)out_size;

    cudaFuncSetAttribute(mgemm<0>, cudaFuncAttributeMaxDynamicSharedMemorySize, SMEM_BYTES);
    cudaFuncSetAttribute(mgemm<1>, cudaFuncAttributeMaxDynamicSharedMemorySize, SMEM_BYTES);
    cudaFuncSetAttribute(mgemm<2>, cudaFuncAttributeMaxDynamicSharedMemorySize, SMEM_BYTES);
    cudaFuncSetAttribute(mgemm<3>, cudaFuncAttributeMaxDynamicSharedMemorySize, SMEM_BYTES);

    fp16 *d_xs_hi, *d_xs_lo, *d_ws, *d_pws;
    cudaGetSymbolAddress((void**)&d_xs_hi, xs_hi);
    cudaGetSymbolAddress((void**)&d_xs_lo, xs_lo);
    cudaGetSymbolAddress((void**)&d_ws,    ws_h);
    cudaGetSymbolAddress((void**)&d_pws,   pws_h);

    dim3 blk(256);

    // 0) prepare operands: x -> hi/lo split; weights -> fp16 cast
    const size_t nx = (size_t)TOK * CDIM, nw = (size_t)QKVN * CDIM, np = (size_t)CDIM * HC;
    split_k<<<(unsigned)((nx / 4 + 255) / 256), blk>>>(x, d_xs_hi, d_xs_lo, nx);
    cast_k <<<(unsigned)((nw / 4 + 255) / 256), blk>>>(qkv_w,  d_ws,  nw);
    cast_k <<<(unsigned)((np / 4 + 255) / 256), blk>>>(proj_w, d_pws, np);

    // 1) QKV projection -> q (scaled hi/lo), k, vt
    mgemm<0><<<dim3(QKVN / 128, TOK / 128, 1), blk, SMEM_BYTES>>>(nullptr, nullptr);
    // 2) S = Q K^T (scale pre-folded)
    mgemm<1><<<dim3(TDIM / 128, TDIM / 128, BH), blk, SMEM_BYTES>>>(nullptr, nullptr);
    // 3) softmax rows -> p hi/lo
    softmax_k<<<BH * TDIM, 256>>>();
    // 4) O = P V -> a hi/lo (proj-ready layout)
    mgemm<2><<<dim3(CDIM / 128, TDIM / 128, BH), blk, SMEM_BYTES>>>(nullptr, nullptr);
    // 5) final projection + bias -> out
    mgemm<3><<<dim3(CDIM / 128, TOK / 128, 1), blk, SMEM_BYTES>>>(out, proj_b);
}